// round 8
// baseline (speedup 1.0000x reference)
#include <cuda_runtime.h>
#include <cuda_bf16.h>
#include <math.h>
#include <stdint.h>
#include <cstdint>

// ---------------------------------------------------------------------------
// MLA forward — bf16x3 GEMMs (cp.async pipeline + ldmatrix) + fused flash attn.
// Shapes: B=1, S=2048, HIDDEN=7168, NH=32, DQ=1536, DKV=512, DH=128, DR=64
// ---------------------------------------------------------------------------

#define S_LEN   2048
#define HIDDEN  7168
#define NH      32
#define DQ      1536
#define DKV     512
#define DH      128
#define DR      64
#define DQR     (DH + DR)            // 192
#define NQCR    (NH * DQR)           // 6144
#define NKV     (NH * 2 * DH)        // 8192
#define DCKV    (DKV + DR)           // 576
#define NODIM   (NH * DH)            // 4096

typedef __nv_bfloat16 bf16;
typedef __nv_bfloat162 bf162;

// ---------------- scratch (device globals; no allocation allowed) ----------
__device__ float g_cq [(long long)S_LEN * DQ];
__device__ float g_qcr[(long long)S_LEN * NQCR];
__device__ float g_ckv[(long long)S_LEN * DCKV];

__device__ bf16 g_Xh [(long long)S_LEN * HIDDEN],  g_Xl [(long long)S_LEN * HIDDEN];
__device__ bf16 g_Wdqh[(long long)HIDDEN * DQ],    g_Wdql[(long long)HIDDEN * DQ];
__device__ bf16 g_Wuqh[(long long)DQ * NQCR],      g_Wuql[(long long)DQ * NQCR];
__device__ bf16 g_Wdkvh[(long long)HIDDEN * DCKV], g_Wdkvl[(long long)HIDDEN * DCKV];
__device__ bf16 g_Wukvh[(long long)DKV * NKV],     g_Wukvl[(long long)DKV * NKV];
__device__ bf16 g_Woh [(long long)NODIM * HIDDEN], g_Wol [(long long)NODIM * HIDDEN];
__device__ bf16 g_cqh [(long long)S_LEN * DQ],     g_cql [(long long)S_LEN * DQ];
__device__ bf16 g_qh  [(long long)S_LEN * NQCR],   g_ql  [(long long)S_LEN * NQCR];
__device__ bf16 g_ckvh[(long long)S_LEN * DCKV],   g_ckvl[(long long)S_LEN * DCKV];
__device__ bf16 g_kvh [(long long)S_LEN * NKV],    g_kvl [(long long)S_LEN * NKV];
__device__ bf16 g_oh  [(long long)S_LEN * NODIM],  g_ol [(long long)S_LEN * NODIM];

// ---------------------------------------------------------------------------
__device__ __forceinline__ void split2(float v, bf16& h, bf16& l)
{
    bf16 hh = __float2bfloat16(v);
    h = hh;
    l = __float2bfloat16(v - __bfloat162float(hh));
}

__device__ __forceinline__ void pack_hl(float a, float b, uint32_t& ph, uint32_t& pl)
{
    bf16 ah = __float2bfloat16(a), bh = __float2bfloat16(b);
    bf16 al = __float2bfloat16(a - __bfloat162float(ah));
    bf16 bl = __float2bfloat16(b - __bfloat162float(bh));
    bf162 H = __halves2bfloat162(ah, bh);
    bf162 L = __halves2bfloat162(al, bl);
    ph = *(uint32_t*)&H;
    pl = *(uint32_t*)&L;
}

// fp32 -> (hi, lo) bf16 split (with optional prescale). n % 4 == 0.
__global__ void split_kernel(const float* __restrict__ s,
                             bf16* __restrict__ h, bf16* __restrict__ l,
                             long long n, float scale)
{
    for (long long i = ((long long)blockIdx.x * blockDim.x + threadIdx.x) * 4;
         i < n; i += (long long)gridDim.x * blockDim.x * 4) {
        float4 v = *(const float4*)(s + i);
        bf16 h0,h1,h2,h3,l0,l1,l2,l3;
        split2(v.x*scale,h0,l0); split2(v.y*scale,h1,l1);
        split2(v.z*scale,h2,l2); split2(v.w*scale,h3,l3);
        *(bf162*)(h + i)     = __halves2bfloat162(h0, h1);
        *(bf162*)(h + i + 2) = __halves2bfloat162(h2, h3);
        *(bf162*)(l + i)     = __halves2bfloat162(l0, l1);
        *(bf162*)(l + i + 2) = __halves2bfloat162(l2, l3);
    }
}

// ---------------------------------------------------------------------------
#define MMA_OP(ac, a, b)                                                     \
    asm volatile("mma.sync.aligned.m16n8k16.row.col.f32.bf16.bf16.f32 "      \
        "{%0,%1,%2,%3}, {%4,%5,%6,%7}, {%8,%9}, {%0,%1,%2,%3};"              \
        : "+f"((ac)[0]), "+f"((ac)[1]), "+f"((ac)[2]), "+f"((ac)[3])         \
        : "r"((a)[0]), "r"((a)[1]), "r"((a)[2]), "r"((a)[3]),                \
          "r"((b)[0]), "r"((b)[1]))

#define MMA_OP2(ac, a, b0v, b1v)                                             \
    asm volatile("mma.sync.aligned.m16n8k16.row.col.f32.bf16.bf16.f32 "      \
        "{%0,%1,%2,%3}, {%4,%5,%6,%7}, {%8,%9}, {%0,%1,%2,%3};"              \
        : "+f"((ac)[0]), "+f"((ac)[1]), "+f"((ac)[2]), "+f"((ac)[3])         \
        : "r"((a)[0]), "r"((a)[1]), "r"((a)[2]), "r"((a)[3]),                \
          "r"(b0v), "r"(b1v))

#define CP16(dst, src) \
    asm volatile("cp.async.cg.shared.global [%0], [%1], 16;" :: "r"(dst), "l"(src))
#define CP_COMMIT() asm volatile("cp.async.commit_group;")
#define CP_WAIT1()  asm volatile("cp.async.wait_group 1;")
#define CP_WAIT0()  asm volatile("cp.async.wait_group 0;")

#define LDSM_X4(f, addr)                                                      \
    asm volatile("ldmatrix.sync.aligned.m8n8.x4.shared.b16 {%0,%1,%2,%3}, [%4];" \
        : "=r"((f)[0]), "=r"((f)[1]), "=r"((f)[2]), "=r"((f)[3]) : "r"(addr))
#define LDSM_X4T(f, addr)                                                     \
    asm volatile("ldmatrix.sync.aligned.m8n8.x4.trans.shared.b16 {%0,%1,%2,%3}, [%4];" \
        : "=r"((f)[0]), "=r"((f)[1]), "=r"((f)[2]), "=r"((f)[3]) : "r"(addr))

// ---------------------------------------------------------------------------
// Batched GEMM, bf16x3 compensated (unchanged from R7 — proven).
// ---------------------------------------------------------------------------
#define A_ST  (128 * 40)
#define B_ST  (32 * 136)
#define STG   (2 * A_ST + 2 * B_ST)
#define SMEM_BYTES (3 * STG * 2)

__global__ __launch_bounds__(256, 1)
void bgemm3(int M, int N, int K,
            const bf16* __restrict__ Ah, const bf16* __restrict__ Al,
            int lda, long long sA,
            const bf16* __restrict__ Bh, const bf16* __restrict__ Bl,
            int ldb, long long sB,
            float* __restrict__ C, bf16* __restrict__ Ch, bf16* __restrict__ Cl,
            int ldc, long long sC, float alpha)
{
    extern __shared__ __align__(16) char dynsmem[];
    uint32_t sbase = (uint32_t)__cvta_generic_to_shared(dynsmem);

    const bf16* pAh = Ah + (long long)blockIdx.z * sA;
    const bf16* pAl = Al + (long long)blockIdx.z * sA;
    const bf16* pBh = Bh + (long long)blockIdx.z * sB;
    const bf16* pBl = Bl + (long long)blockIdx.z * sB;

    const int tid = threadIdx.x;
    const int bm = blockIdx.y << 7;
    const int bn = blockIdx.x << 7;

    const int lane = tid & 31;
    const int warp = tid >> 5;
    const int wm = (warp & 3) << 5;
    const int wn = (warp >> 2) << 6;
    const int g  = lane >> 2;
    const int qt = (lane & 3) << 1;

    const int nk = K >> 5;

    float acc[2][8][4];
#pragma unroll
    for (int i = 0; i < 2; i++)
#pragma unroll
        for (int j = 0; j < 8; j++)
#pragma unroll
            for (int c = 0; c < 4; c++) acc[i][j][c] = 0.f;

    auto issue_stage = [&](int stg, int k0) {
        uint32_t sb = sbase + (uint32_t)(stg * STG * 2);
#pragma unroll
        for (int r = 0; r < 2; r++) {
            const int c = tid + (r << 8);
            const int arow = c >> 2;
            const int ak   = (c & 3) << 3;
            const long long aoff = (long long)(bm + arow) * lda + k0 + ak;
            const uint32_t dA = sb + (uint32_t)((arow * 40 + ak) * 2);
            CP16(dA,            pAh + aoff);
            CP16(dA + A_ST * 2, pAl + aoff);
            const int krow = c >> 4;
            const int nc   = (c & 15) << 3;
            int gn = bn + nc;
            if (gn > N - 8) gn = N - 8;
            const long long boff = (long long)(k0 + krow) * ldb + gn;
            const uint32_t dB = sb + (uint32_t)((2 * A_ST + krow * 136 + nc) * 2);
            CP16(dB,            pBh + boff);
            CP16(dB + B_ST * 2, pBl + boff);
        }
    };

    issue_stage(0, 0);
    CP_COMMIT();
    if (nk > 1) issue_stage(1, 32);
    CP_COMMIT();

    const int ar  = lane & 15;
    const int hi8 = (lane & 16) >> 1;

    for (int kt = 0; kt < nk; kt++) {
        CP_WAIT1();
        __syncthreads();

        if (kt + 2 < nk) issue_stage((kt + 2) % 3, (kt + 2) << 5);
        CP_COMMIT();

        const uint32_t sb = sbase + (uint32_t)((kt % 3) * STG * 2);
        const uint32_t aH = sb;
        const uint32_t aL = sb + A_ST * 2;
        const uint32_t bH = sb + 2 * A_ST * 2;
        const uint32_t bL = sb + (2 * A_ST + B_ST) * 2;

#pragma unroll
        for (int ks = 0; ks < 2; ks++) {
            const int ka = (ks << 4) + hi8;
            const uint32_t adr0 = aH + (uint32_t)(((wm + ar) * 40 + ka) * 2);
            uint32_t afH0[4], afH1[4];
            LDSM_X4(afH0, adr0);
            LDSM_X4(afH1, adr0 + 16 * 80);

            const int kb = (ks << 4) + ar;
            const uint32_t bdr = bH + (uint32_t)((kb * 136 + wn + hi8) * 2);
            uint32_t bfH[8][2];
#pragma unroll
            for (int jp = 0; jp < 4; jp++) {
                uint32_t t4[4];
                LDSM_X4T(t4, bdr + jp * 32);
                bfH[2*jp][0] = t4[0]; bfH[2*jp][1] = t4[1];
                bfH[2*jp+1][0] = t4[2]; bfH[2*jp+1][1] = t4[3];
            }
#pragma unroll
            for (int jn = 0; jn < 8; jn++) {
                MMA_OP(acc[0][jn], afH0, bfH[jn]);
                MMA_OP(acc[1][jn], afH1, bfH[jn]);
            }

            const uint32_t bdrL = bL + (uint32_t)((kb * 136 + wn + hi8) * 2);
            uint32_t bfL[8][2];
#pragma unroll
            for (int jp = 0; jp < 4; jp++) {
                uint32_t t4[4];
                LDSM_X4T(t4, bdrL + jp * 32);
                bfL[2*jp][0] = t4[0]; bfL[2*jp][1] = t4[1];
                bfL[2*jp+1][0] = t4[2]; bfL[2*jp+1][1] = t4[3];
            }
#pragma unroll
            for (int jn = 0; jn < 8; jn++) {
                MMA_OP(acc[0][jn], afH0, bfL[jn]);
                MMA_OP(acc[1][jn], afH1, bfL[jn]);
            }

            const uint32_t adrL = aL + (uint32_t)(((wm + ar) * 40 + ka) * 2);
            uint32_t afL0[4], afL1[4];
            LDSM_X4(afL0, adrL);
            LDSM_X4(afL1, adrL + 16 * 80);
#pragma unroll
            for (int jn = 0; jn < 8; jn++) {
                MMA_OP(acc[0][jn], afL0, bfH[jn]);
                MMA_OP(acc[1][jn], afL1, bfH[jn]);
            }
        }
    }

    float* pC = C ? C + (long long)blockIdx.z * sC : (float*)0;
    bf16* pCh = Ch ? Ch + (long long)blockIdx.z * sC : (bf16*)0;
    bf16* pCl = Cl ? Cl + (long long)blockIdx.z * sC : (bf16*)0;

#pragma unroll
    for (int im = 0; im < 2; im++) {
#pragma unroll
        for (int jn = 0; jn < 8; jn++) {
            const int row = bm + wm + (im << 4) + g;
            const int col = bn + wn + (jn << 3) + qt;
            if (col < N) {
                const float v0 = alpha * acc[im][jn][0];
                const float v1 = alpha * acc[im][jn][1];
                const float v2 = alpha * acc[im][jn][2];
                const float v3 = alpha * acc[im][jn][3];
                if (pC) {
                    *(float2*)(pC + (long long)row * ldc + col) = make_float2(v0, v1);
                    *(float2*)(pC + (long long)(row + 8) * ldc + col) = make_float2(v2, v3);
                }
                if (pCh) {
                    bf16 h0,h1,h2,h3,l0,l1,l2,l3;
                    split2(v0,h0,l0); split2(v1,h1,l1);
                    split2(v2,h2,l2); split2(v3,h3,l3);
                    *(bf162*)(pCh + (long long)row * ldc + col) = __halves2bfloat162(h0, h1);
                    *(bf162*)(pCl + (long long)row * ldc + col) = __halves2bfloat162(l0, l1);
                    *(bf162*)(pCh + (long long)(row + 8) * ldc + col) = __halves2bfloat162(h2, h3);
                    *(bf162*)(pCl + (long long)(row + 8) * ldc + col) = __halves2bfloat162(l2, l3);
                }
            }
        }
    }
}

// ---------------------------------------------------------------------------
// Fused flash attention: per (q-tile 128, head). 8 warps x 16 q-rows.
// K streamed in 64-key tiles (192-d), V in 64x128 tiles, bf16x3 everywhere.
// Q smem [row][192] stride 200; K smem [key][192] stride 200; V [key][128] str 136.
// Scale is pre-folded into Q (qh/ql).
// ---------------------------------------------------------------------------
#define FA_OQH 0u
#define FA_OQL 51200u
#define FA_OKH 102400u
#define FA_OKL 128000u
#define FA_OVH 153600u
#define FA_OVL 171008u
#define FA_SMEM 188416

__global__ __launch_bounds__(256, 1)
void flash_kernel(const bf16* __restrict__ Qh, const bf16* __restrict__ Ql,
                  const bf16* __restrict__ KVh, const bf16* __restrict__ KVl,
                  const bf16* __restrict__ CKh, const bf16* __restrict__ CKl,
                  bf16* __restrict__ Oh, bf16* __restrict__ Ol)
{
    extern __shared__ __align__(16) char sm[];
    const uint32_t sb = (uint32_t)__cvta_generic_to_shared(sm);

    const int tid  = threadIdx.x;
    const int lane = tid & 31;
    const int warp = tid >> 5;
    const int q0 = blockIdx.x << 7;
    const int h  = blockIdx.y;
    const int g  = lane >> 2;
    const int q2 = (lane & 3) << 1;
    const int wm = warp << 4;
    const int ar  = lane & 15;
    const int hi8 = (lane & 16) >> 1;

    // ---- Q tile load ----
    for (int idx = tid; idx < 128 * 24; idx += 256) {
        const int row = idx / 24, c = idx % 24;
        const long long src = (long long)(q0 + row) * NQCR + h * DQR + c * 8;
        const uint32_t dst = (uint32_t)((row * 200 + c * 8) * 2);
        CP16(sb + FA_OQH + dst, Qh + src);
        CP16(sb + FA_OQL + dst, Ql + src);
    }
    CP_COMMIT();

    auto load_K = [&](int k0) {
        for (int idx = tid; idx < 64 * 24; idx += 256) {
            const int row = idx / 24, c = idx % 24;
            const uint32_t dst = (uint32_t)((row * 200 + c * 8) * 2);
            if (c < 16) {
                const long long src = (long long)(k0 + row) * NKV + h * 256 + c * 8;
                CP16(sb + FA_OKH + dst, KVh + src);
                CP16(sb + FA_OKL + dst, KVl + src);
            } else {
                const long long src = (long long)(k0 + row) * DCKV + DKV + (c - 16) * 8;
                CP16(sb + FA_OKH + dst, CKh + src);
                CP16(sb + FA_OKL + dst, CKl + src);
            }
        }
    };
    auto load_V = [&](int k0) {
        for (int idx = tid; idx < 64 * 16; idx += 256) {
            const int row = idx >> 4, c = idx & 15;
            const long long src = (long long)(k0 + row) * NKV + h * 256 + 128 + c * 8;
            const uint32_t dst = (uint32_t)((row * 136 + c * 8) * 2);
            CP16(sb + FA_OVH + dst, KVh + src);
            CP16(sb + FA_OVL + dst, KVl + src);
        }
    };

    load_K(0);
    CP_COMMIT();
    load_V(0);
    CP_COMMIT();

    float o[16][4];
#pragma unroll
    for (int j = 0; j < 16; j++)
#pragma unroll
        for (int c = 0; c < 4; c++) o[j][c] = 0.f;
    float m0 = -3.402823466e+38f, m1 = -3.402823466e+38f;
    float l0 = 0.f, l1 = 0.f;

    const int NIT = S_LEN / 64;
    for (int it = 0; it < NIT; it++) {
        // ---- S = Q K^T ----
        CP_WAIT1();                 // K_it resident (V_it may pend)
        __syncthreads();

        float s[8][4];
#pragma unroll
        for (int j = 0; j < 8; j++)
#pragma unroll
            for (int c = 0; c < 4; c++) s[j][c] = 0.f;

        // K B-frag lane addressing (non-trans ldmatrix on [key][d]):
        const int krow_l = ((lane >> 4) << 3) + (lane & 7);
        const int kcol_l = ((lane >> 3) & 1) << 3;

#pragma unroll
        for (int kt = 0; kt < 12; kt++) {
            uint32_t aH[4], aL[4];
            const uint32_t qadr = sb + FA_OQH +
                (uint32_t)(((wm + ar) * 200 + kt * 16 + hi8) * 2);
            LDSM_X4(aH, qadr);
            LDSM_X4(aL, qadr + (FA_OQL - FA_OQH));

#pragma unroll
            for (int np = 0; np < 4; np++) {
                const uint32_t kadr = sb + FA_OKH +
                    (uint32_t)(((np * 16 + krow_l) * 200 + kt * 16 + kcol_l) * 2);
                uint32_t kH[4], kL[4];
                LDSM_X4(kH, kadr);
                LDSM_X4(kL, kadr + (FA_OKL - FA_OKH));
                MMA_OP2(s[2*np],   aH, kH[0], kH[1]);
                MMA_OP2(s[2*np+1], aH, kH[2], kH[3]);
                MMA_OP2(s[2*np],   aH, kL[0], kL[1]);
                MMA_OP2(s[2*np+1], aH, kL[2], kL[3]);
                MMA_OP2(s[2*np],   aL, kH[0], kH[1]);
                MMA_OP2(s[2*np+1], aL, kH[2], kH[3]);
            }
        }

        __syncthreads();            // all warps done reading K smem
        if (it + 1 < NIT) load_K((it + 1) * 64);
        CP_COMMIT();                // (possibly empty group — keeps counting uniform)

        // ---- online softmax (scale already folded into Q) ----
        float mx0 = -3.402823466e+38f, mx1 = -3.402823466e+38f;
#pragma unroll
        for (int j = 0; j < 8; j++) {
            mx0 = fmaxf(mx0, fmaxf(s[j][0], s[j][1]));
            mx1 = fmaxf(mx1, fmaxf(s[j][2], s[j][3]));
        }
        mx0 = fmaxf(mx0, __shfl_xor_sync(0xffffffffu, mx0, 1));
        mx0 = fmaxf(mx0, __shfl_xor_sync(0xffffffffu, mx0, 2));
        mx1 = fmaxf(mx1, __shfl_xor_sync(0xffffffffu, mx1, 1));
        mx1 = fmaxf(mx1, __shfl_xor_sync(0xffffffffu, mx1, 2));

        const float mn0 = fmaxf(m0, mx0), mn1 = fmaxf(m1, mx1);
        const float c0 = __expf(m0 - mn0), c1 = __expf(m1 - mn1);
        float sum0 = 0.f, sum1 = 0.f;
#pragma unroll
        for (int j = 0; j < 8; j++) {
            s[j][0] = __expf(s[j][0] - mn0);
            s[j][1] = __expf(s[j][1] - mn0);
            s[j][2] = __expf(s[j][2] - mn1);
            s[j][3] = __expf(s[j][3] - mn1);
            sum0 += s[j][0] + s[j][1];
            sum1 += s[j][2] + s[j][3];
        }
        sum0 += __shfl_xor_sync(0xffffffffu, sum0, 1);
        sum0 += __shfl_xor_sync(0xffffffffu, sum0, 2);
        sum1 += __shfl_xor_sync(0xffffffffu, sum1, 1);
        sum1 += __shfl_xor_sync(0xffffffffu, sum1, 2);
        l0 = l0 * c0 + sum0;
        l1 = l1 * c1 + sum1;
        m0 = mn0;
        m1 = mn1;
#pragma unroll
        for (int j = 0; j < 16; j++) {
            o[j][0] *= c0; o[j][1] *= c0;
            o[j][2] *= c1; o[j][3] *= c1;
        }

        // ---- O += P V ----
        CP_WAIT1();                 // V_it resident (K_{it+1} may pend)
        __syncthreads();

#pragma unroll
        for (int t = 0; t < 4; t++) {
            uint32_t pa_h[4], pa_l[4];
            pack_hl(s[2*t][0],   s[2*t][1],   pa_h[0], pa_l[0]);
            pack_hl(s[2*t][2],   s[2*t][3],   pa_h[1], pa_l[1]);
            pack_hl(s[2*t+1][0], s[2*t+1][1], pa_h[2], pa_l[2]);
            pack_hl(s[2*t+1][2], s[2*t+1][3], pa_h[3], pa_l[3]);

#pragma unroll
            for (int np = 0; np < 8; np++) {
                const uint32_t vadr = sb + FA_OVH +
                    (uint32_t)(((t * 16 + ar) * 136 + np * 16 + hi8) * 2);
                uint32_t vH[4], vL[4];
                LDSM_X4T(vH, vadr);
                LDSM_X4T(vL, vadr + (FA_OVL - FA_OVH));
                MMA_OP2(o[2*np],   pa_h, vH[0], vH[1]);
                MMA_OP2(o[2*np+1], pa_h, vH[2], vH[3]);
                MMA_OP2(o[2*np],   pa_h, vL[0], vL[1]);
                MMA_OP2(o[2*np+1], pa_h, vL[2], vL[3]);
                MMA_OP2(o[2*np],   pa_l, vH[0], vH[1]);
                MMA_OP2(o[2*np+1], pa_l, vH[2], vH[3]);
            }
        }

        __syncthreads();            // all warps done reading V smem
        if (it + 1 < NIT) load_V((it + 1) * 64);
        CP_COMMIT();
    }

    // ---- epilogue: normalize + write hi/lo bf16 ----
    const float r0 = 1.f / l0, r1 = 1.f / l1;
    const int row0 = q0 + wm + g;
#pragma unroll
    for (int j = 0; j < 16; j++) {
        const int col = h * DH + j * 8 + q2;
        bf16 hh0, ll0, hh1, ll1;
        split2(o[j][0] * r0, hh0, ll0);
        split2(o[j][1] * r0, hh1, ll1);
        *(bf162*)(Oh + (long long)row0 * NODIM + col) = __halves2bfloat162(hh0, hh1);
        *(bf162*)(Ol + (long long)row0 * NODIM + col) = __halves2bfloat162(ll0, ll1);
        split2(o[j][2] * r1, hh0, ll0);
        split2(o[j][3] * r1, hh1, ll1);
        *(bf162*)(Oh + (long long)(row0 + 8) * NODIM + col) = __halves2bfloat162(hh0, hh1);
        *(bf162*)(Ol + (long long)(row0 + 8) * NODIM + col) = __halves2bfloat162(ll0, ll1);
    }
}

// ---------------------------------------------------------------------------
// RMSNorm over first W cols (row stride ld), output hi/lo bf16 split.
// ---------------------------------------------------------------------------
__global__ void rmsnorm_split_kernel(const float* __restrict__ x,
                                     const float* __restrict__ g,
                                     int W, int ld,
                                     bf16* __restrict__ oh, bf16* __restrict__ ol)
{
    __shared__ float red[32];
    const float* row = x + (long long)blockIdx.x * ld;
    float s = 0.f;
    for (int i = threadIdx.x; i < W; i += blockDim.x) {
        float v = row[i];
        s += v * v;
    }
#pragma unroll
    for (int o = 16; o; o >>= 1) s += __shfl_xor_sync(0xffffffffu, s, o);
    int w = threadIdx.x >> 5, l = threadIdx.x & 31;
    if (l == 0) red[w] = s;
    __syncthreads();
    if (w == 0) {
        float t = (l < (blockDim.x >> 5)) ? red[l] : 0.f;
#pragma unroll
        for (int o = 16; o; o >>= 1) t += __shfl_xor_sync(0xffffffffu, t, o);
        if (l == 0) red[0] = t;
    }
    __syncthreads();
    float scale = rsqrtf(red[0] / (float)W + 1.1920929e-07f);
    bf16* ohr = oh + (long long)blockIdx.x * ld;
    bf16* olr = ol + (long long)blockIdx.x * ld;
    for (int i = threadIdx.x; i < W; i += blockDim.x) {
        bf16 hh, ll;
        split2(row[i] * scale * g[i], hh, ll);
        ohr[i] = hh;
        olr[i] = ll;
    }
}

// ---------------------------------------------------------------------------
// RoPE (D=64)
// ---------------------------------------------------------------------------
__device__ __forceinline__ void rope_pair(float* base, int j, int t)
{
    float ex  = (2.0f * (float)j) / 64.0f;
    float inv = 1.0f / powf(10000.0f, ex);
    float fr  = (float)t * inv;
    float c   = cosf(fr);
    float sn  = sinf(fr);
    float x1 = base[j];
    float x2 = base[j + 32];
    base[j]      = x1 * c - x2 * sn;
    base[j + 32] = x2 * c + x1 * sn;
}

__global__ void rope_q_kernel(float* __restrict__ qcr)
{
    int item = blockIdx.x * (blockDim.x >> 5) + (threadIdx.x >> 5);
    if (item >= S_LEN * NH) return;
    int s = item >> 5;
    int h = item & 31;
    int j = threadIdx.x & 31;
    rope_pair(qcr + (long long)s * NQCR + h * DQR + DH, j, s);
}

// rope on ckv cols 512..575 in place + hi/lo split out
__global__ void rope_k_kernel(float* __restrict__ ckv,
                              bf16* __restrict__ oh, bf16* __restrict__ ol)
{
    int item = blockIdx.x * (blockDim.x >> 5) + (threadIdx.x >> 5);
    if (item >= S_LEN) return;
    int j = threadIdx.x & 31;
    float* base = ckv + (long long)item * DCKV + DKV;
    rope_pair(base, j, item);
    bf16 hh, ll;
    split2(base[j], hh, ll);
    oh[(long long)item * DCKV + DKV + j] = hh;
    ol[(long long)item * DCKV + DKV + j] = ll;
    split2(base[j + 32], hh, ll);
    oh[(long long)item * DCKV + DKV + j + 32] = hh;
    ol[(long long)item * DCKV + DKV + j + 32] = ll;
}

// ---------------------------------------------------------------------------
static inline int split_grid(long long n)
{
    long long b = (n / 4 + 255) / 256;
    if (b > 8192) b = 8192;
    return (int)b;
}

extern "C" void kernel_launch(void* const* d_in, const int* in_sizes, int n_in,
                              void* d_out, int out_size)
{
    const float* X     = (const float*)d_in[0];
    const float* W_dq  = (const float*)d_in[1];
    const float* gq    = (const float*)d_in[2];
    const float* W_uq  = (const float*)d_in[3];
    const float* W_dkv = (const float*)d_in[4];
    const float* gkv   = (const float*)d_in[5];
    const float* W_ukv = (const float*)d_in[6];
    const float* W_o   = (const float*)d_in[7];
    float* out = (float*)d_out;

    float *cq, *qcr, *ckv;
    bf16 *Xh,*Xl,*Wdqh,*Wdql,*Wuqh,*Wuql,*Wdkvh,*Wdkvl,*Wukvh,*Wukvl,*Woh,*Wol;
    bf16 *cqh,*cql,*qh,*ql,*ckvh,*ckvl,*kvh,*kvl,*oh,*ol;

    cudaGetSymbolAddress((void**)&cq,  g_cq);
    cudaGetSymbolAddress((void**)&qcr, g_qcr);
    cudaGetSymbolAddress((void**)&ckv, g_ckv);
    cudaGetSymbolAddress((void**)&Xh,  g_Xh);   cudaGetSymbolAddress((void**)&Xl,  g_Xl);
    cudaGetSymbolAddress((void**)&Wdqh, g_Wdqh);  cudaGetSymbolAddress((void**)&Wdql, g_Wdql);
    cudaGetSymbolAddress((void**)&Wuqh, g_Wuqh);  cudaGetSymbolAddress((void**)&Wuql, g_Wuql);
    cudaGetSymbolAddress((void**)&Wdkvh, g_Wdkvh); cudaGetSymbolAddress((void**)&Wdkvl, g_Wdkvl);
    cudaGetSymbolAddress((void**)&Wukvh, g_Wukvh); cudaGetSymbolAddress((void**)&Wukvl, g_Wukvl);
    cudaGetSymbolAddress((void**)&Woh, g_Woh);   cudaGetSymbolAddress((void**)&Wol, g_Wol);
    cudaGetSymbolAddress((void**)&cqh, g_cqh);   cudaGetSymbolAddress((void**)&cql, g_cql);
    cudaGetSymbolAddress((void**)&qh,  g_qh);    cudaGetSymbolAddress((void**)&ql,  g_ql);
    cudaGetSymbolAddress((void**)&ckvh, g_ckvh); cudaGetSymbolAddress((void**)&ckvl, g_ckvl);
    cudaGetSymbolAddress((void**)&kvh, g_kvh);   cudaGetSymbolAddress((void**)&kvl, g_kvl);
    cudaGetSymbolAddress((void**)&oh,  g_oh);    cudaGetSymbolAddress((void**)&ol,  g_ol);

    cudaFuncSetAttribute(bgemm3, cudaFuncAttributeMaxDynamicSharedMemorySize, SMEM_BYTES);
    cudaFuncSetAttribute(flash_kernel, cudaFuncAttributeMaxDynamicSharedMemorySize, FA_SMEM);

    dim3 blk(256);
    const int SB = SMEM_BYTES;
    const float scale = 1.0f / sqrtf((float)DQR);

    // ---- split inputs to bf16 hi/lo ----
    long long nX = (long long)S_LEN * HIDDEN;
    split_kernel<<<split_grid(nX), blk>>>(X, Xh, Xl, nX, 1.f);
    long long nWdq = (long long)HIDDEN * DQ;
    split_kernel<<<split_grid(nWdq), blk>>>(W_dq, Wdqh, Wdql, nWdq, 1.f);
    long long nWuq = (long long)DQ * NQCR;
    split_kernel<<<split_grid(nWuq), blk>>>(W_uq, Wuqh, Wuql, nWuq, 1.f);
    long long nWdkv = (long long)HIDDEN * DCKV;
    split_kernel<<<split_grid(nWdkv), blk>>>(W_dkv, Wdkvh, Wdkvl, nWdkv, 1.f);
    long long nWukv = (long long)DKV * NKV;
    split_kernel<<<split_grid(nWukv), blk>>>(W_ukv, Wukvh, Wukvl, nWukv, 1.f);
    long long nWo = (long long)NODIM * HIDDEN;
    split_kernel<<<split_grid(nWo), blk>>>(W_o, Woh, Wol, nWo, 1.f);

    // ---- G1: c_q = X @ W_dq ----
    bgemm3<<<dim3(DQ / 128, S_LEN / 128, 1), blk, SB>>>(
        S_LEN, DQ, HIDDEN, Xh, Xl, HIDDEN, 0, Wdqh, Wdql, DQ, 0,
        cq, (bf16*)0, (bf16*)0, DQ, 0, 1.f);

    rmsnorm_split_kernel<<<S_LEN, 256>>>(cq, gq, DQ, DQ, cqh, cql);

    // ---- G2: qcr = rmsnorm(c_q) @ W_uq ----
    bgemm3<<<dim3(NQCR / 128, S_LEN / 128, 1), blk, SB>>>(
        S_LEN, NQCR, DQ, cqh, cql, DQ, 0, Wuqh, Wuql, NQCR, 0,
        qcr, (bf16*)0, (bf16*)0, NQCR, 0, 1.f);

    rope_q_kernel<<<(S_LEN * NH) / 8, 256>>>(qcr);
    // split with softmax scale folded into Q
    long long nq = (long long)S_LEN * NQCR;
    split_kernel<<<split_grid(nq), blk>>>(qcr, qh, ql, nq, scale);

    // ---- G3: ckv_kr = X @ W_dkv ----
    bgemm3<<<dim3((DCKV + 127) / 128, S_LEN / 128, 1), blk, SB>>>(
        S_LEN, DCKV, HIDDEN, Xh, Xl, HIDDEN, 0, Wdkvh, Wdkvl, DCKV, 0,
        ckv, (bf16*)0, (bf16*)0, DCKV, 0, 1.f);

    rmsnorm_split_kernel<<<S_LEN, 256>>>(ckv, gkv, DKV, DCKV, ckvh, ckvl);
    rope_k_kernel<<<S_LEN / 8, 256>>>(ckv, ckvh, ckvl);

    // ---- G4: kv = rmsnorm(c_kv) @ W_ukv (hi/lo only) ----
    bgemm3<<<dim3(NKV / 128, S_LEN / 128, 1), blk, SB>>>(
        S_LEN, NKV, DKV, ckvh, ckvl, DCKV, 0, Wukvh, Wukvl, NKV, 0,
        (float*)0, kvh, kvl, NKV, 0, 1.f);

    // ---- fused flash attention: oh/ol = softmax(QK^T)V ----
    flash_kernel<<<dim3(S_LEN / 128, NH), blk, FA_SMEM>>>(
        qh, ql, kvh, kvl, ckvh, ckvl, oh, ol);

    // ---- G7: out = O @ W_o ----
    bgemm3<<<dim3(HIDDEN / 128, S_LEN / 128, 1), blk, SB>>>(
        S_LEN, HIDDEN, NODIM, oh, ol, NODIM, 0, Woh, Wol, HIDDEN, 0,
        out, (bf16*)0, (bf16*)0, HIDDEN, 0, 1.f);
}

// round 9
// speedup vs baseline: 1.3933x; 1.3933x over previous
#include <cuda_runtime.h>
#include <cuda_bf16.h>
#include <math.h>
#include <stdint.h>
#include <cstdint>

// ---------------------------------------------------------------------------
// MLA forward — bf16x3 GEMMs via mma.sync + cp.async 3-stage pipeline + ldmatrix.
// Materialized attention (flash variant regressed), smem single-pass softmax.
// Shapes: B=1, S=2048, HIDDEN=7168, NH=32, DQ=1536, DKV=512, DH=128, DR=64
// ---------------------------------------------------------------------------

#define S_LEN   2048
#define HIDDEN  7168
#define NH      32
#define DQ      1536
#define DKV     512
#define DH      128
#define DR      64
#define DQR     (DH + DR)            // 192
#define NQCR    (NH * DQR)           // 6144
#define NKV     (NH * 2 * DH)        // 8192
#define DCKV    (DKV + DR)           // 576
#define NODIM   (NH * DH)            // 4096

typedef __nv_bfloat16 bf16;
typedef __nv_bfloat162 bf162;

// ---------------- scratch (device globals; no allocation allowed) ----------
__device__ float g_cq [(long long)S_LEN * DQ];
__device__ float g_qcr[(long long)S_LEN * NQCR];
__device__ float g_ckv[(long long)S_LEN * DCKV];
__device__ float g_kv [(long long)S_LEN * NKV];
__device__ float g_sc [(long long)NH * S_LEN * S_LEN];

__device__ bf16 g_Xh [(long long)S_LEN * HIDDEN],  g_Xl [(long long)S_LEN * HIDDEN];
__device__ bf16 g_Wdqh[(long long)HIDDEN * DQ],    g_Wdql[(long long)HIDDEN * DQ];
__device__ bf16 g_Wuqh[(long long)DQ * NQCR],      g_Wuql[(long long)DQ * NQCR];
__device__ bf16 g_Wdkvh[(long long)HIDDEN * DCKV], g_Wdkvl[(long long)HIDDEN * DCKV];
__device__ bf16 g_Wukvh[(long long)DKV * NKV],     g_Wukvl[(long long)DKV * NKV];
__device__ bf16 g_Woh [(long long)NODIM * HIDDEN], g_Wol [(long long)NODIM * HIDDEN];
__device__ bf16 g_cqh [(long long)S_LEN * DQ],     g_cql [(long long)S_LEN * DQ];
__device__ bf16 g_qh  [(long long)S_LEN * NQCR],   g_ql  [(long long)S_LEN * NQCR];
__device__ bf16 g_ckvh[(long long)S_LEN * DCKV],   g_ckvl[(long long)S_LEN * DCKV];
__device__ bf16 g_kvh [(long long)S_LEN * NKV],    g_kvl [(long long)S_LEN * NKV];
__device__ bf16 g_kTh [(long long)NH * DQR * S_LEN], g_kTl[(long long)NH * DQR * S_LEN];
__device__ bf16 g_Ph  [(long long)NH * S_LEN * S_LEN], g_Pl[(long long)NH * S_LEN * S_LEN];
__device__ bf16 g_oh  [(long long)S_LEN * NODIM],  g_ol [(long long)S_LEN * NODIM];

// ---------------------------------------------------------------------------
__device__ __forceinline__ void split2(float v, bf16& h, bf16& l)
{
    bf16 hh = __float2bfloat16(v);
    h = hh;
    l = __float2bfloat16(v - __bfloat162float(hh));
}

// fp32 -> (hi, lo) bf16 split. n % 4 == 0 at all call sites.
__global__ void split_kernel(const float* __restrict__ s,
                             bf16* __restrict__ h, bf16* __restrict__ l,
                             long long n)
{
    for (long long i = ((long long)blockIdx.x * blockDim.x + threadIdx.x) * 4;
         i < n; i += (long long)gridDim.x * blockDim.x * 4) {
        float4 v = *(const float4*)(s + i);
        bf16 h0,h1,h2,h3,l0,l1,l2,l3;
        split2(v.x,h0,l0); split2(v.y,h1,l1); split2(v.z,h2,l2); split2(v.w,h3,l3);
        *(bf162*)(h + i)     = __halves2bfloat162(h0, h1);
        *(bf162*)(h + i + 2) = __halves2bfloat162(h2, h3);
        *(bf162*)(l + i)     = __halves2bfloat162(l0, l1);
        *(bf162*)(l + i + 2) = __halves2bfloat162(l2, l3);
    }
}

// ---------------------------------------------------------------------------
#define MMA_OP(ac, a, b)                                                     \
    asm volatile("mma.sync.aligned.m16n8k16.row.col.f32.bf16.bf16.f32 "      \
        "{%0,%1,%2,%3}, {%4,%5,%6,%7}, {%8,%9}, {%0,%1,%2,%3};"              \
        : "+f"((ac)[0]), "+f"((ac)[1]), "+f"((ac)[2]), "+f"((ac)[3])         \
        : "r"((a)[0]), "r"((a)[1]), "r"((a)[2]), "r"((a)[3]),                \
          "r"((b)[0]), "r"((b)[1]))

#define CP16(dst, src) \
    asm volatile("cp.async.cg.shared.global [%0], [%1], 16;" :: "r"(dst), "l"(src))
#define CP_COMMIT() asm volatile("cp.async.commit_group;")
#define CP_WAIT1()  asm volatile("cp.async.wait_group 1;")

#define LDSM_X4(f, addr)                                                      \
    asm volatile("ldmatrix.sync.aligned.m8n8.x4.shared.b16 {%0,%1,%2,%3}, [%4];" \
        : "=r"((f)[0]), "=r"((f)[1]), "=r"((f)[2]), "=r"((f)[3]) : "r"(addr))
#define LDSM_X4T(r0, r1, r2, r3, addr)                                        \
    asm volatile("ldmatrix.sync.aligned.m8n8.x4.trans.shared.b16 {%0,%1,%2,%3}, [%4];" \
        : "=r"(r0), "=r"(r1), "=r"(r2), "=r"(r3) : "r"(addr))

// ---------------------------------------------------------------------------
// Batched GEMM, bf16x3 compensated: C = alpha * (Ah·Bh + Ah·Bl + Al·Bh).
// 128x128 tile, BK=32, 3-stage cp.async, 256 threads, 8 warps of 32x64.
// ---------------------------------------------------------------------------
#define A_ST  (128 * 40)
#define B_ST  (32 * 136)
#define STG   (2 * A_ST + 2 * B_ST)
#define SMEM_BYTES (3 * STG * 2)

__global__ __launch_bounds__(256, 1)
void bgemm3(int M, int N, int K,
            const bf16* __restrict__ Ah, const bf16* __restrict__ Al,
            int lda, long long sA,
            const bf16* __restrict__ Bh, const bf16* __restrict__ Bl,
            int ldb, long long sB,
            float* __restrict__ C, bf16* __restrict__ Ch, bf16* __restrict__ Cl,
            int ldc, long long sC, float alpha)
{
    extern __shared__ __align__(16) char dynsmem[];
    uint32_t sbase = (uint32_t)__cvta_generic_to_shared(dynsmem);

    const bf16* pAh = Ah + (long long)blockIdx.z * sA;
    const bf16* pAl = Al + (long long)blockIdx.z * sA;
    const bf16* pBh = Bh + (long long)blockIdx.z * sB;
    const bf16* pBl = Bl + (long long)blockIdx.z * sB;

    const int tid = threadIdx.x;
    const int bm = blockIdx.y << 7;
    const int bn = blockIdx.x << 7;

    const int lane = tid & 31;
    const int warp = tid >> 5;
    const int wm = (warp & 3) << 5;
    const int wn = (warp >> 2) << 6;
    const int g  = lane >> 2;
    const int qt = (lane & 3) << 1;

    const int nk = K >> 5;

    float acc[2][8][4];
#pragma unroll
    for (int i = 0; i < 2; i++)
#pragma unroll
        for (int j = 0; j < 8; j++)
#pragma unroll
            for (int c = 0; c < 4; c++) acc[i][j][c] = 0.f;

    auto issue_stage = [&](int stg, int k0) {
        uint32_t sb = sbase + (uint32_t)(stg * STG * 2);
#pragma unroll
        for (int r = 0; r < 2; r++) {
            const int c = tid + (r << 8);
            const int arow = c >> 2;
            const int ak   = (c & 3) << 3;
            const long long aoff = (long long)(bm + arow) * lda + k0 + ak;
            const uint32_t dA = sb + (uint32_t)((arow * 40 + ak) * 2);
            CP16(dA,            pAh + aoff);
            CP16(dA + A_ST * 2, pAl + aoff);
            const int krow = c >> 4;
            const int nc   = (c & 15) << 3;
            int gn = bn + nc;
            if (gn > N - 8) gn = N - 8;
            const long long boff = (long long)(k0 + krow) * ldb + gn;
            const uint32_t dB = sb + (uint32_t)((2 * A_ST + krow * 136 + nc) * 2);
            CP16(dB,            pBh + boff);
            CP16(dB + B_ST * 2, pBl + boff);
        }
    };

    issue_stage(0, 0);
    CP_COMMIT();
    if (nk > 1) issue_stage(1, 32);
    CP_COMMIT();

    const int ar  = lane & 15;
    const int hi8 = (lane & 16) >> 1;

    for (int kt = 0; kt < nk; kt++) {
        CP_WAIT1();
        __syncthreads();

        if (kt + 2 < nk) issue_stage((kt + 2) % 3, (kt + 2) << 5);
        CP_COMMIT();

        const uint32_t sb = sbase + (uint32_t)((kt % 3) * STG * 2);
        const uint32_t aH = sb;
        const uint32_t aL = sb + A_ST * 2;
        const uint32_t bH = sb + 2 * A_ST * 2;
        const uint32_t bL = sb + (2 * A_ST + B_ST) * 2;

#pragma unroll
        for (int ks = 0; ks < 2; ks++) {
            const int ka = (ks << 4) + hi8;
            const uint32_t adr0 = aH + (uint32_t)(((wm + ar) * 40 + ka) * 2);
            uint32_t afH0[4], afH1[4];
            LDSM_X4(afH0, adr0);
            LDSM_X4(afH1, adr0 + 16 * 80);

            const int kb = (ks << 4) + ar;
            const uint32_t bdr = bH + (uint32_t)((kb * 136 + wn + hi8) * 2);
            uint32_t bfH[8][2];
#pragma unroll
            for (int jp = 0; jp < 4; jp++)
                LDSM_X4T(bfH[2*jp][0], bfH[2*jp][1], bfH[2*jp+1][0], bfH[2*jp+1][1],
                         bdr + jp * 32);
#pragma unroll
            for (int jn = 0; jn < 8; jn++) {
                MMA_OP(acc[0][jn], afH0, bfH[jn]);
                MMA_OP(acc[1][jn], afH1, bfH[jn]);
            }

            const uint32_t bdrL = bL + (uint32_t)((kb * 136 + wn + hi8) * 2);
            uint32_t bfL[8][2];
#pragma unroll
            for (int jp = 0; jp < 4; jp++)
                LDSM_X4T(bfL[2*jp][0], bfL[2*jp][1], bfL[2*jp+1][0], bfL[2*jp+1][1],
                         bdrL + jp * 32);
#pragma unroll
            for (int jn = 0; jn < 8; jn++) {
                MMA_OP(acc[0][jn], afH0, bfL[jn]);
                MMA_OP(acc[1][jn], afH1, bfL[jn]);
            }

            const uint32_t adrL = aL + (uint32_t)(((wm + ar) * 40 + ka) * 2);
            uint32_t afL0[4], afL1[4];
            LDSM_X4(afL0, adrL);
            LDSM_X4(afL1, adrL + 16 * 80);
#pragma unroll
            for (int jn = 0; jn < 8; jn++) {
                MMA_OP(acc[0][jn], afL0, bfH[jn]);
                MMA_OP(acc[1][jn], afL1, bfH[jn]);
            }
        }
    }

    float* pC = C ? C + (long long)blockIdx.z * sC : (float*)0;
    bf16* pCh = Ch ? Ch + (long long)blockIdx.z * sC : (bf16*)0;
    bf16* pCl = Cl ? Cl + (long long)blockIdx.z * sC : (bf16*)0;

#pragma unroll
    for (int im = 0; im < 2; im++) {
#pragma unroll
        for (int jn = 0; jn < 8; jn++) {
            const int row = bm + wm + (im << 4) + g;
            const int col = bn + wn + (jn << 3) + qt;
            if (col < N) {
                const float v0 = alpha * acc[im][jn][0];
                const float v1 = alpha * acc[im][jn][1];
                const float v2 = alpha * acc[im][jn][2];
                const float v3 = alpha * acc[im][jn][3];
                if (pC) {
                    *(float2*)(pC + (long long)row * ldc + col) = make_float2(v0, v1);
                    *(float2*)(pC + (long long)(row + 8) * ldc + col) = make_float2(v2, v3);
                }
                if (pCh) {
                    bf16 h0,h1,h2,h3,l0,l1,l2,l3;
                    split2(v0,h0,l0); split2(v1,h1,l1);
                    split2(v2,h2,l2); split2(v3,h3,l3);
                    *(bf162*)(pCh + (long long)row * ldc + col) = __halves2bfloat162(h0, h1);
                    *(bf162*)(pCl + (long long)row * ldc + col) = __halves2bfloat162(l0, l1);
                    *(bf162*)(pCh + (long long)(row + 8) * ldc + col) = __halves2bfloat162(h2, h3);
                    *(bf162*)(pCl + (long long)(row + 8) * ldc + col) = __halves2bfloat162(l2, l3);
                }
            }
        }
    }
}

// ---------------------------------------------------------------------------
// RMSNorm over first W cols (row stride ld), output hi/lo bf16 split.
// ---------------------------------------------------------------------------
__global__ void rmsnorm_split_kernel(const float* __restrict__ x,
                                     const float* __restrict__ g,
                                     int W, int ld,
                                     bf16* __restrict__ oh, bf16* __restrict__ ol)
{
    __shared__ float red[32];
    const float* row = x + (long long)blockIdx.x * ld;
    float s = 0.f;
    for (int i = threadIdx.x; i < W; i += blockDim.x) {
        float v = row[i];
        s += v * v;
    }
#pragma unroll
    for (int o = 16; o; o >>= 1) s += __shfl_xor_sync(0xffffffffu, s, o);
    int w = threadIdx.x >> 5, l = threadIdx.x & 31;
    if (l == 0) red[w] = s;
    __syncthreads();
    if (w == 0) {
        float t = (l < (blockDim.x >> 5)) ? red[l] : 0.f;
#pragma unroll
        for (int o = 16; o; o >>= 1) t += __shfl_xor_sync(0xffffffffu, t, o);
        if (l == 0) red[0] = t;
    }
    __syncthreads();
    float scale = rsqrtf(red[0] / (float)W + 1.1920929e-07f);
    bf16* ohr = oh + (long long)blockIdx.x * ld;
    bf16* olr = ol + (long long)blockIdx.x * ld;
    for (int i = threadIdx.x; i < W; i += blockDim.x) {
        bf16 hh, ll;
        split2(row[i] * scale * g[i], hh, ll);
        ohr[i] = hh;
        olr[i] = ll;
    }
}

// ---------------------------------------------------------------------------
// RoPE (D=64)
// ---------------------------------------------------------------------------
__device__ __forceinline__ void rope_pair(float* base, int j, int t)
{
    float ex  = (2.0f * (float)j) / 64.0f;
    float inv = 1.0f / powf(10000.0f, ex);
    float fr  = (float)t * inv;
    float c   = cosf(fr);
    float sn  = sinf(fr);
    float x1 = base[j];
    float x2 = base[j + 32];
    base[j]      = x1 * c - x2 * sn;
    base[j + 32] = x2 * c + x1 * sn;
}

__global__ void rope_q_kernel(float* __restrict__ qcr)
{
    int item = blockIdx.x * (blockDim.x >> 5) + (threadIdx.x >> 5);
    if (item >= S_LEN * NH) return;
    int s = item >> 5;
    int h = item & 31;
    int j = threadIdx.x & 31;
    rope_pair(qcr + (long long)s * NQCR + h * DQR + DH, j, s);
}

// rope on ckv cols 512..575 in place + hi/lo split out
__global__ void rope_k_kernel(float* __restrict__ ckv,
                              bf16* __restrict__ oh, bf16* __restrict__ ol)
{
    int item = blockIdx.x * (blockDim.x >> 5) + (threadIdx.x >> 5);
    if (item >= S_LEN) return;
    int j = threadIdx.x & 31;
    float* base = ckv + (long long)item * DCKV + DKV;
    rope_pair(base, j, item);
    bf16 hh, ll;
    split2(base[j], hh, ll);
    oh[(long long)item * DCKV + DKV + j] = hh;
    ol[(long long)item * DCKV + DKV + j] = ll;
    split2(base[j + 32], hh, ll);
    oh[(long long)item * DCKV + DKV + j + 32] = hh;
    ol[(long long)item * DCKV + DKV + j + 32] = ll;
}

// ---------------------------------------------------------------------------
// kT[h][d][s] hi/lo from fp32 kv + roped ckv.
// ---------------------------------------------------------------------------
__global__ void build_kT_split(const float* __restrict__ kv,
                               const float* __restrict__ ckv,
                               bf16* __restrict__ kTh, bf16* __restrict__ kTl)
{
    const long long total = (long long)NH * DQR * S_LEN;
    for (long long i = (long long)blockIdx.x * blockDim.x + threadIdx.x;
         i < total; i += (long long)gridDim.x * blockDim.x) {
        int s = (int)(i % S_LEN);
        long long t = i / S_LEN;
        int d = (int)(t % DQR);
        int h = (int)(t / DQR);
        float v;
        if (d < DH) v = kv[(long long)s * NKV + h * 2 * DH + d];
        else        v = ckv[(long long)s * DCKV + DKV + (d - DH)];
        bf16 hh, ll;
        split2(v, hh, ll);
        kTh[i] = hh;
        kTl[i] = ll;
    }
}

// ---------------------------------------------------------------------------
// Single-pass smem softmax (width 2048): one read of sc, one write of Ph/Pl.
// One block (256 threads) per row; row cached in 8 KB smem.
// ---------------------------------------------------------------------------
__global__ __launch_bounds__(256)
void softmax_fused_kernel(const float* __restrict__ sc,
                          bf16* __restrict__ ph, bf16* __restrict__ pl)
{
    __shared__ float srow[S_LEN];
    __shared__ float red[32];
    const float* row = sc + (long long)blockIdx.x * S_LEN;
    bf16* hrow = ph + (long long)blockIdx.x * S_LEN;
    bf16* lrow = pl + (long long)blockIdx.x * S_LEN;
    const int w = threadIdx.x >> 5, l = threadIdx.x & 31;

    // ---- load row to smem + max ----
    float m = -3.402823466e+38f;
#pragma unroll
    for (int r = 0; r < 2; r++) {
        const int i = (threadIdx.x + (r << 8)) << 2;
        float4 v = *(const float4*)(row + i);
        *(float4*)(srow + i) = v;
        m = fmaxf(m, fmaxf(fmaxf(v.x, v.y), fmaxf(v.z, v.w)));
    }
#pragma unroll
    for (int o = 16; o; o >>= 1) m = fmaxf(m, __shfl_xor_sync(0xffffffffu, m, o));
    if (l == 0) red[w] = m;
    __syncthreads();
    if (w == 0) {
        float t = (l < 8) ? red[l] : -3.402823466e+38f;
#pragma unroll
        for (int o = 16; o; o >>= 1) t = fmaxf(t, __shfl_xor_sync(0xffffffffu, t, o));
        if (l == 0) red[0] = t;
    }
    __syncthreads();
    const float M = red[0];

    // ---- exp (in smem) + sum ----
    float s = 0.f;
#pragma unroll
    for (int r = 0; r < 2; r++) {
        const int i = (threadIdx.x + (r << 8)) << 2;
        float4 v = *(float4*)(srow + i);
        v.x = __expf(v.x - M);
        v.y = __expf(v.y - M);
        v.z = __expf(v.z - M);
        v.w = __expf(v.w - M);
        *(float4*)(srow + i) = v;
        s += (v.x + v.y) + (v.z + v.w);
    }
#pragma unroll
    for (int o = 16; o; o >>= 1) s += __shfl_xor_sync(0xffffffffu, s, o);
    if (l == 0) red[w] = s;
    __syncthreads();
    if (w == 0) {
        float t = (l < 8) ? red[l] : 0.f;
#pragma unroll
        for (int o = 16; o; o >>= 1) t += __shfl_xor_sync(0xffffffffu, t, o);
        if (l == 0) red[0] = t;
    }
    __syncthreads();
    const float inv = 1.0f / red[0];

    // ---- normalize + hi/lo split write ----
#pragma unroll
    for (int r = 0; r < 2; r++) {
        const int i = (threadIdx.x + (r << 8)) << 2;
        float4 v = *(float4*)(srow + i);
        bf16 h0,h1,h2,h3,l0,l1,l2,l3;
        split2(v.x * inv, h0, l0);
        split2(v.y * inv, h1, l1);
        split2(v.z * inv, h2, l2);
        split2(v.w * inv, h3, l3);
        *(bf162*)(hrow + i)     = __halves2bfloat162(h0, h1);
        *(bf162*)(hrow + i + 2) = __halves2bfloat162(h2, h3);
        *(bf162*)(lrow + i)     = __halves2bfloat162(l0, l1);
        *(bf162*)(lrow + i + 2) = __halves2bfloat162(l2, l3);
    }
}

// ---------------------------------------------------------------------------
static inline int split_grid(long long n)
{
    long long b = (n / 4 + 255) / 256;
    if (b > 8192) b = 8192;
    return (int)b;
}

extern "C" void kernel_launch(void* const* d_in, const int* in_sizes, int n_in,
                              void* d_out, int out_size)
{
    const float* X     = (const float*)d_in[0];
    const float* W_dq  = (const float*)d_in[1];
    const float* gq    = (const float*)d_in[2];
    const float* W_uq  = (const float*)d_in[3];
    const float* W_dkv = (const float*)d_in[4];
    const float* gkv   = (const float*)d_in[5];
    const float* W_ukv = (const float*)d_in[6];
    const float* W_o   = (const float*)d_in[7];
    float* out = (float*)d_out;

    float *cq, *qcr, *ckv, *kv, *sc;
    bf16 *Xh,*Xl,*Wdqh,*Wdql,*Wuqh,*Wuql,*Wdkvh,*Wdkvl,*Wukvh,*Wukvl,*Woh,*Wol;
    bf16 *cqh,*cql,*qh,*ql,*ckvh,*ckvl,*kvh,*kvl,*kTh,*kTl,*Ph,*Pl,*oh,*ol;

    cudaGetSymbolAddress((void**)&cq,  g_cq);
    cudaGetSymbolAddress((void**)&qcr, g_qcr);
    cudaGetSymbolAddress((void**)&ckv, g_ckv);
    cudaGetSymbolAddress((void**)&kv,  g_kv);
    cudaGetSymbolAddress((void**)&sc,  g_sc);
    cudaGetSymbolAddress((void**)&Xh,  g_Xh);   cudaGetSymbolAddress((void**)&Xl,  g_Xl);
    cudaGetSymbolAddress((void**)&Wdqh, g_Wdqh);  cudaGetSymbolAddress((void**)&Wdql, g_Wdql);
    cudaGetSymbolAddress((void**)&Wuqh, g_Wuqh);  cudaGetSymbolAddress((void**)&Wuql, g_Wuql);
    cudaGetSymbolAddress((void**)&Wdkvh, g_Wdkvh); cudaGetSymbolAddress((void**)&Wdkvl, g_Wdkvl);
    cudaGetSymbolAddress((void**)&Wukvh, g_Wukvh); cudaGetSymbolAddress((void**)&Wukvl, g_Wukvl);
    cudaGetSymbolAddress((void**)&Woh, g_Woh);   cudaGetSymbolAddress((void**)&Wol, g_Wol);
    cudaGetSymbolAddress((void**)&cqh, g_cqh);   cudaGetSymbolAddress((void**)&cql, g_cql);
    cudaGetSymbolAddress((void**)&qh,  g_qh);    cudaGetSymbolAddress((void**)&ql,  g_ql);
    cudaGetSymbolAddress((void**)&ckvh, g_ckvh); cudaGetSymbolAddress((void**)&ckvl, g_ckvl);
    cudaGetSymbolAddress((void**)&kvh, g_kvh);   cudaGetSymbolAddress((void**)&kvl, g_kvl);
    cudaGetSymbolAddress((void**)&kTh, g_kTh);   cudaGetSymbolAddress((void**)&kTl, g_kTl);
    cudaGetSymbolAddress((void**)&Ph,  g_Ph);    cudaGetSymbolAddress((void**)&Pl,  g_Pl);
    cudaGetSymbolAddress((void**)&oh,  g_oh);    cudaGetSymbolAddress((void**)&ol,  g_ol);

    cudaFuncSetAttribute(bgemm3, cudaFuncAttributeMaxDynamicSharedMemorySize, SMEM_BYTES);

    dim3 blk(256);
    const int SB = SMEM_BYTES;

    // ---- split inputs to bf16 hi/lo ----
    long long nX = (long long)S_LEN * HIDDEN;
    split_kernel<<<split_grid(nX), blk>>>(X, Xh, Xl, nX);
    long long nWdq = (long long)HIDDEN * DQ;
    split_kernel<<<split_grid(nWdq), blk>>>(W_dq, Wdqh, Wdql, nWdq);
    long long nWuq = (long long)DQ * NQCR;
    split_kernel<<<split_grid(nWuq), blk>>>(W_uq, Wuqh, Wuql, nWuq);
    long long nWdkv = (long long)HIDDEN * DCKV;
    split_kernel<<<split_grid(nWdkv), blk>>>(W_dkv, Wdkvh, Wdkvl, nWdkv);
    long long nWukv = (long long)DKV * NKV;
    split_kernel<<<split_grid(nWukv), blk>>>(W_ukv, Wukvh, Wukvl, nWukv);
    long long nWo = (long long)NODIM * HIDDEN;
    split_kernel<<<split_grid(nWo), blk>>>(W_o, Woh, Wol, nWo);

    // ---- G1: c_q = X @ W_dq ----
    bgemm3<<<dim3(DQ / 128, S_LEN / 128, 1), blk, SB>>>(
        S_LEN, DQ, HIDDEN, Xh, Xl, HIDDEN, 0, Wdqh, Wdql, DQ, 0,
        cq, (bf16*)0, (bf16*)0, DQ, 0, 1.f);

    rmsnorm_split_kernel<<<S_LEN, 256>>>(cq, gq, DQ, DQ, cqh, cql);

    // ---- G2: qcr = rmsnorm(c_q) @ W_uq ----
    bgemm3<<<dim3(NQCR / 128, S_LEN / 128, 1), blk, SB>>>(
        S_LEN, NQCR, DQ, cqh, cql, DQ, 0, Wuqh, Wuql, NQCR, 0,
        qcr, (bf16*)0, (bf16*)0, NQCR, 0, 1.f);

    rope_q_kernel<<<(S_LEN * NH) / 8, 256>>>(qcr);
    long long nq = (long long)S_LEN * NQCR;
    split_kernel<<<split_grid(nq), blk>>>(qcr, qh, ql, nq);

    // ---- G3: ckv_kr = X @ W_dkv ----
    bgemm3<<<dim3((DCKV + 127) / 128, S_LEN / 128, 1), blk, SB>>>(
        S_LEN, DCKV, HIDDEN, Xh, Xl, HIDDEN, 0, Wdkvh, Wdkvl, DCKV, 0,
        ckv, (bf16*)0, (bf16*)0, DCKV, 0, 1.f);

    rmsnorm_split_kernel<<<S_LEN, 256>>>(ckv, gkv, DKV, DCKV, ckvh, ckvl);
    rope_k_kernel<<<S_LEN / 8, 256>>>(ckv, ckvh, ckvl);

    // ---- G4: kv = rmsnorm(c_kv) @ W_ukv (epilogue emits fp32 + hi/lo) ----
    bgemm3<<<dim3(NKV / 128, S_LEN / 128, 1), blk, SB>>>(
        S_LEN, NKV, DKV, ckvh, ckvl, DCKV, 0, Wukvh, Wukvl, NKV, 0,
        kv, kvh, kvl, NKV, 0, 1.f);

    build_kT_split<<<4096, 256>>>(kv, ckv, kTh, kTl);

    // ---- G5: scores[h] = Q[h] @ K[h]^T * scale ----
    float scale = 1.0f / sqrtf((float)DQR);
    bgemm3<<<dim3(S_LEN / 128, S_LEN / 128, NH), blk, SB>>>(
        S_LEN, S_LEN, DQR,
        qh, ql, NQCR, (long long)DQR,
        kTh, kTl, S_LEN, (long long)DQR * S_LEN,
        sc, (bf16*)0, (bf16*)0, S_LEN, (long long)S_LEN * S_LEN, scale);

    // ---- single-pass softmax + P hi/lo split ----
    softmax_fused_kernel<<<NH * S_LEN, 256>>>(sc, Ph, Pl);

    // ---- G6: O[h] = P[h] @ V[h] (epilogue emits hi/lo only) ----
    bgemm3<<<dim3(1, S_LEN / 128, NH), blk, SB>>>(
        S_LEN, DH, S_LEN,
        Ph, Pl, S_LEN, (long long)S_LEN * S_LEN,
        kvh + DH, kvl + DH, NKV, (long long)2 * DH,
        (float*)0, oh, ol, NODIM, (long long)DH, 1.f);

    // ---- G7: out = O @ W_o ----
    bgemm3<<<dim3(HIDDEN / 128, S_LEN / 128, 1), blk, SB>>>(
        S_LEN, HIDDEN, NODIM, oh, ol, NODIM, 0, Woh, Wol, HIDDEN, 0,
        out, (bf16*)0, (bf16*)0, HIDDEN, 0, 1.f);
}

// round 13
// speedup vs baseline: 1.8702x; 1.3422x over previous
#include <cuda_runtime.h>
#include <cuda_fp16.h>
#include <math.h>
#include <stdint.h>
#include <cstdint>

// ---------------------------------------------------------------------------
// MLA forward — fp16 A-split 2-pass GEMMs (C = Ah·B + Al·B, B single fp16)
// via mma.sync m16n8k16.f16 + cp.async 3-stage pipeline + ldmatrix.
// Shapes: B=1, S=2048, HIDDEN=7168, NH=32, DQ=1536, DKV=512, DH=128, DR=64
// ---------------------------------------------------------------------------

#define S_LEN   2048
#define HIDDEN  7168
#define NH      32
#define DQ      1536
#define DKV     512
#define DH      128
#define DR      64
#define DQR     (DH + DR)            // 192
#define NQCR    (NH * DQR)           // 6144
#define NKV     (NH * 2 * DH)        // 8192
#define DCKV    (DKV + DR)           // 576
#define NODIM   (NH * DH)            // 4096

typedef __half h16;

// ---------------- scratch (device globals; no allocation allowed) ----------
__device__ float g_cq [(long long)S_LEN * DQ];
__device__ float g_qcr[(long long)S_LEN * NQCR];
__device__ float g_ckv[(long long)S_LEN * DCKV];
__device__ float g_sc [(long long)NH * S_LEN * S_LEN];

__device__ h16 g_Xh [(long long)S_LEN * HIDDEN],  g_Xl [(long long)S_LEN * HIDDEN];
__device__ h16 g_Wdq [(long long)HIDDEN * DQ];          // B-side: single fp16
__device__ h16 g_Wuq [(long long)DQ * NQCR];
__device__ h16 g_Wdkv[(long long)HIDDEN * DCKV];
__device__ h16 g_Wukv[(long long)DKV * NKV];
__device__ h16 g_Wo  [(long long)NODIM * HIDDEN];
__device__ h16 g_cqh [(long long)S_LEN * DQ],     g_cql [(long long)S_LEN * DQ];
__device__ h16 g_qh  [(long long)S_LEN * NQCR],   g_ql  [(long long)S_LEN * NQCR];
__device__ h16 g_ckvnh[(long long)S_LEN * DKV],   g_ckvnl[(long long)S_LEN * DKV];
__device__ h16 g_krh [(long long)S_LEN * DR];           // roped k_r, single
__device__ h16 g_kvh [(long long)S_LEN * NKV];          // kv, single (B-side)
__device__ h16 g_kTh [(long long)NH * DQR * S_LEN];     // K^T, single (B-side)
__device__ h16 g_Ph  [(long long)NH * S_LEN * S_LEN], g_Pl[(long long)NH * S_LEN * S_LEN];
__device__ h16 g_oh  [(long long)S_LEN * NODIM],  g_ol [(long long)S_LEN * NODIM];

// ---------------------------------------------------------------------------
__device__ __forceinline__ void split2h(float v, h16& h, h16& l)
{
    h16 hh = __float2half_rn(v);
    h = hh;
    l = __float2half_rn(v - __half2float(hh));
}

// fp32 -> fp16 hi/lo split. n % 4 == 0.
__global__ void split16_kernel(const float* __restrict__ s,
                               h16* __restrict__ h, h16* __restrict__ l,
                               long long n)
{
    for (long long i = ((long long)blockIdx.x * blockDim.x + threadIdx.x) * 4;
         i < n; i += (long long)gridDim.x * blockDim.x * 4) {
        float4 v = *(const float4*)(s + i);
        h16 h0,h1,h2,h3,l0,l1,l2,l3;
        split2h(v.x,h0,l0); split2h(v.y,h1,l1); split2h(v.z,h2,l2); split2h(v.w,h3,l3);
        *(half2*)(h + i)     = __halves2half2(h0, h1);
        *(half2*)(h + i + 2) = __halves2half2(h2, h3);
        *(half2*)(l + i)     = __halves2half2(l0, l1);
        *(half2*)(l + i + 2) = __halves2half2(l2, l3);
    }
}

// fp32 -> fp16 single quantize. n % 4 == 0.
__global__ void quant16_kernel(const float* __restrict__ s,
                               h16* __restrict__ h, long long n)
{
    for (long long i = ((long long)blockIdx.x * blockDim.x + threadIdx.x) * 4;
         i < n; i += (long long)gridDim.x * blockDim.x * 4) {
        float4 v = *(const float4*)(s + i);
        *(half2*)(h + i)     = __halves2half2(__float2half_rn(v.x), __float2half_rn(v.y));
        *(half2*)(h + i + 2) = __halves2half2(__float2half_rn(v.z), __float2half_rn(v.w));
    }
}

// ---------------------------------------------------------------------------
#define MMA_OP(ac, a, b)                                                     \
    asm volatile("mma.sync.aligned.m16n8k16.row.col.f32.f16.f16.f32 "        \
        "{%0,%1,%2,%3}, {%4,%5,%6,%7}, {%8,%9}, {%0,%1,%2,%3};"              \
        : "+f"((ac)[0]), "+f"((ac)[1]), "+f"((ac)[2]), "+f"((ac)[3])         \
        : "r"((a)[0]), "r"((a)[1]), "r"((a)[2]), "r"((a)[3]),                \
          "r"((b)[0]), "r"((b)[1]))

#define CP16(dst, src) \
    asm volatile("cp.async.cg.shared.global [%0], [%1], 16;" :: "r"(dst), "l"(src))
#define CP_COMMIT() asm volatile("cp.async.commit_group;")
#define CP_WAIT1()  asm volatile("cp.async.wait_group 1;")

#define LDSM_X4(f, addr)                                                      \
    asm volatile("ldmatrix.sync.aligned.m8n8.x4.shared.b16 {%0,%1,%2,%3}, [%4];" \
        : "=r"((f)[0]), "=r"((f)[1]), "=r"((f)[2]), "=r"((f)[3]) : "r"(addr))
#define LDSM_X4T(r0, r1, r2, r3, addr)                                        \
    asm volatile("ldmatrix.sync.aligned.m8n8.x4.trans.shared.b16 {%0,%1,%2,%3}, [%4];" \
        : "=r"(r0), "=r"(r1), "=r"(r2), "=r"(r3) : "r"(addr))

// ---------------------------------------------------------------------------
// GEMM, fp16 A-split 2-pass: C = alpha * (Ah·B + Al·B). B single fp16.
// 128x128 tile, BK=32, 3-stage cp.async, 256 threads, 8 warps of 32x64.
// A [M][K] k-contig hi/lo. B [K][N] n-contig single.
// Outputs: fp32 C and/or fp16 Ch (+ optional Cl hi/lo pair).
// M%128==0, K%32==0, N%8==0 effective (clamped loads), lda/ldb%8==0.
// ---------------------------------------------------------------------------
#define A_ST  (128 * 40)
#define B_ST  (32 * 136)
#define STG   (2 * A_ST + B_ST)               // 14592 elems
#define SMEM_BYTES (3 * STG * 2)              // 87552 bytes

__global__ __launch_bounds__(256, 1)
void bgemm2(int M, int N, int K,
            const h16* __restrict__ Ah, const h16* __restrict__ Al,
            int lda, long long sA,
            const h16* __restrict__ B, int ldb, long long sB,
            float* __restrict__ C, h16* __restrict__ Ch, h16* __restrict__ Cl,
            int ldc, long long sC, float alpha)
{
    extern __shared__ __align__(16) char dynsmem[];
    uint32_t sbase = (uint32_t)__cvta_generic_to_shared(dynsmem);

    const h16* pAh = Ah + (long long)blockIdx.z * sA;
    const h16* pAl = Al + (long long)blockIdx.z * sA;
    const h16* pB  = B  + (long long)blockIdx.z * sB;

    const int tid = threadIdx.x;
    const int bm = blockIdx.y << 7;
    const int bn = blockIdx.x << 7;

    const int lane = tid & 31;
    const int warp = tid >> 5;
    const int wm = (warp & 3) << 5;
    const int wn = (warp >> 2) << 6;
    const int g  = lane >> 2;
    const int qt = (lane & 3) << 1;

    const int nk = K >> 5;

    float acc[2][8][4];
#pragma unroll
    for (int i = 0; i < 2; i++)
#pragma unroll
        for (int j = 0; j < 8; j++)
#pragma unroll
            for (int c = 0; c < 4; c++) acc[i][j][c] = 0.f;

    auto issue_stage = [&](int stg, int k0) {
        uint32_t sb = sbase + (uint32_t)(stg * STG * 2);
#pragma unroll
        for (int r = 0; r < 2; r++) {
            const int c = tid + (r << 8);
            // A hi/lo: row = c/4, k-chunk = (c%4)*8
            const int arow = c >> 2;
            const int ak   = (c & 3) << 3;
            const long long aoff = (long long)(bm + arow) * lda + k0 + ak;
            const uint32_t dA = sb + (uint32_t)((arow * 40 + ak) * 2);
            CP16(dA,            pAh + aoff);
            CP16(dA + A_ST * 2, pAl + aoff);
            // B single: k-row = c/16, n-chunk = (c%16)*8
            const int krow = c >> 4;
            const int nc   = (c & 15) << 3;
            int gn = bn + nc;
            if (gn > N - 8) gn = N - 8;
            const long long boff = (long long)(k0 + krow) * ldb + gn;
            const uint32_t dB = sb + (uint32_t)((2 * A_ST + krow * 136 + nc) * 2);
            CP16(dB, pB + boff);
        }
    };

    issue_stage(0, 0);
    CP_COMMIT();
    if (nk > 1) issue_stage(1, 32);
    CP_COMMIT();

    const int ar  = lane & 15;
    const int hi8 = (lane & 16) >> 1;

    for (int kt = 0; kt < nk; kt++) {
        CP_WAIT1();
        __syncthreads();

        if (kt + 2 < nk) issue_stage((kt + 2) % 3, (kt + 2) << 5);
        CP_COMMIT();

        const uint32_t sb = sbase + (uint32_t)((kt % 3) * STG * 2);
        const uint32_t aH = sb;
        const uint32_t aL = sb + A_ST * 2;
        const uint32_t bB = sb + 2 * A_ST * 2;

#pragma unroll
        for (int ks = 0; ks < 2; ks++) {
            const int ka = (ks << 4) + hi8;
            const uint32_t adr0 = aH + (uint32_t)(((wm + ar) * 40 + ka) * 2);
            uint32_t afH0[4], afH1[4];
            LDSM_X4(afH0, adr0);
            LDSM_X4(afH1, adr0 + 16 * 80);

            const int kb = (ks << 4) + ar;
            const uint32_t bdr = bB + (uint32_t)((kb * 136 + wn + hi8) * 2);
            uint32_t bf[8][2];
#pragma unroll
            for (int jp = 0; jp < 4; jp++)
                LDSM_X4T(bf[2*jp][0], bf[2*jp][1], bf[2*jp+1][0], bf[2*jp+1][1],
                         bdr + jp * 32);

            // pass 1: Ah * B
#pragma unroll
            for (int jn = 0; jn < 8; jn++) {
                MMA_OP(acc[0][jn], afH0, bf[jn]);
                MMA_OP(acc[1][jn], afH1, bf[jn]);
            }

            // pass 2: Al * B (B fragments reused)
            const uint32_t adrL = aL + (uint32_t)(((wm + ar) * 40 + ka) * 2);
            uint32_t afL0[4], afL1[4];
            LDSM_X4(afL0, adrL);
            LDSM_X4(afL1, adrL + 16 * 80);
#pragma unroll
            for (int jn = 0; jn < 8; jn++) {
                MMA_OP(acc[0][jn], afL0, bf[jn]);
                MMA_OP(acc[1][jn], afL1, bf[jn]);
            }
        }
    }

    float* pC = C ? C + (long long)blockIdx.z * sC : (float*)0;
    h16* pCh = Ch ? Ch + (long long)blockIdx.z * sC : (h16*)0;
    h16* pCl = Cl ? Cl + (long long)blockIdx.z * sC : (h16*)0;

#pragma unroll
    for (int im = 0; im < 2; im++) {
#pragma unroll
        for (int jn = 0; jn < 8; jn++) {
            const int row = bm + wm + (im << 4) + g;
            const int col = bn + wn + (jn << 3) + qt;
            if (col < N) {
                const float v0 = alpha * acc[im][jn][0];
                const float v1 = alpha * acc[im][jn][1];
                const float v2 = alpha * acc[im][jn][2];
                const float v3 = alpha * acc[im][jn][3];
                if (pC) {
                    *(float2*)(pC + (long long)row * ldc + col) = make_float2(v0, v1);
                    *(float2*)(pC + (long long)(row + 8) * ldc + col) = make_float2(v2, v3);
                }
                if (pCh && pCl) {
                    h16 h0,h1,h2,h3,l0,l1,l2,l3;
                    split2h(v0,h0,l0); split2h(v1,h1,l1);
                    split2h(v2,h2,l2); split2h(v3,h3,l3);
                    *(half2*)(pCh + (long long)row * ldc + col) = __halves2half2(h0, h1);
                    *(half2*)(pCl + (long long)row * ldc + col) = __halves2half2(l0, l1);
                    *(half2*)(pCh + (long long)(row + 8) * ldc + col) = __halves2half2(h2, h3);
                    *(half2*)(pCl + (long long)(row + 8) * ldc + col) = __halves2half2(l2, l3);
                } else if (pCh) {
                    *(half2*)(pCh + (long long)row * ldc + col) =
                        __halves2half2(__float2half_rn(v0), __float2half_rn(v1));
                    *(half2*)(pCh + (long long)(row + 8) * ldc + col) =
                        __halves2half2(__float2half_rn(v2), __float2half_rn(v3));
                }
            }
        }
    }
}

// ---------------------------------------------------------------------------
// RMSNorm over first W cols (row stride ld in, ldo out), fp16 hi/lo out.
// ---------------------------------------------------------------------------
__global__ void rmsnorm_split_kernel(const float* __restrict__ x,
                                     const float* __restrict__ g,
                                     int W, int ld, int ldo,
                                     h16* __restrict__ oh, h16* __restrict__ ol)
{
    __shared__ float red[32];
    const float* row = x + (long long)blockIdx.x * ld;
    float s = 0.f;
    for (int i = threadIdx.x; i < W; i += blockDim.x) {
        float v = row[i];
        s += v * v;
    }
#pragma unroll
    for (int o = 16; o; o >>= 1) s += __shfl_xor_sync(0xffffffffu, s, o);
    int w = threadIdx.x >> 5, l = threadIdx.x & 31;
    if (l == 0) red[w] = s;
    __syncthreads();
    if (w == 0) {
        float t = (l < (blockDim.x >> 5)) ? red[l] : 0.f;
#pragma unroll
        for (int o = 16; o; o >>= 1) t += __shfl_xor_sync(0xffffffffu, t, o);
        if (l == 0) red[0] = t;
    }
    __syncthreads();
    float scale = rsqrtf(red[0] / (float)W + 1.1920929e-07f);
    h16* ohr = oh + (long long)blockIdx.x * ldo;
    h16* olr = ol + (long long)blockIdx.x * ldo;
    for (int i = threadIdx.x; i < W; i += blockDim.x) {
        h16 hh, ll;
        split2h(row[i] * scale * g[i], hh, ll);
        ohr[i] = hh;
        olr[i] = ll;
    }
}

// ---------------------------------------------------------------------------
// RoPE (D=64)
// ---------------------------------------------------------------------------
__device__ __forceinline__ void rope_pair(float* base, int j, int t)
{
    float ex  = (2.0f * (float)j) / 64.0f;
    float inv = 1.0f / powf(10000.0f, ex);
    float fr  = (float)t * inv;
    float c   = cosf(fr);
    float sn  = sinf(fr);
    float x1 = base[j];
    float x2 = base[j + 32];
    base[j]      = x1 * c - x2 * sn;
    base[j + 32] = x2 * c + x1 * sn;
}

__global__ void rope_q_kernel(float* __restrict__ qcr)
{
    int item = blockIdx.x * (blockDim.x >> 5) + (threadIdx.x >> 5);
    if (item >= S_LEN * NH) return;
    int s = item >> 5;
    int h = item & 31;
    int j = threadIdx.x & 31;
    rope_pair(qcr + (long long)s * NQCR + h * DQR + DH, j, s);
}

// rope on ckv cols 512..575, write single fp16 k_r
__global__ void rope_k_kernel(float* __restrict__ ckv, h16* __restrict__ krh)
{
    int item = blockIdx.x * (blockDim.x >> 5) + (threadIdx.x >> 5);
    if (item >= S_LEN) return;
    int j = threadIdx.x & 31;
    float* base = ckv + (long long)item * DCKV + DKV;
    rope_pair(base, j, item);
    krh[(long long)item * DR + j]      = __float2half_rn(base[j]);
    krh[(long long)item * DR + j + 32] = __float2half_rn(base[j + 32]);
}

// ---------------------------------------------------------------------------
// kT[h][d][s] single fp16 from kv fp16 + roped k_r fp16.
// ---------------------------------------------------------------------------
__global__ void build_kT_kernel(const h16* __restrict__ kvh,
                                const h16* __restrict__ krh,
                                h16* __restrict__ kTh)
{
    const long long total = (long long)NH * DQR * S_LEN;
    for (long long i = (long long)blockIdx.x * blockDim.x + threadIdx.x;
         i < total; i += (long long)gridDim.x * blockDim.x) {
        int s = (int)(i % S_LEN);
        long long t = i / S_LEN;
        int d = (int)(t % DQR);
        int h = (int)(t / DQR);
        kTh[i] = (d < DH) ? kvh[(long long)s * NKV + h * 2 * DH + d]
                          : krh[(long long)s * DR + (d - DH)];
    }
}

// ---------------------------------------------------------------------------
// Single-pass smem softmax (width 2048) + fp16 hi/lo split output.
// ---------------------------------------------------------------------------
__global__ __launch_bounds__(256)
void softmax_fused_kernel(const float* __restrict__ sc,
                          h16* __restrict__ ph, h16* __restrict__ pl)
{
    __shared__ float srow[S_LEN];
    __shared__ float red[32];
    const float* row = sc + (long long)blockIdx.x * S_LEN;
    h16* hrow = ph + (long long)blockIdx.x * S_LEN;
    h16* lrow = pl + (long long)blockIdx.x * S_LEN;
    const int w = threadIdx.x >> 5, l = threadIdx.x & 31;

    float m = -3.402823466e+38f;
#pragma unroll
    for (int r = 0; r < 2; r++) {
        const int i = (threadIdx.x + (r << 8)) << 2;
        float4 v = *(const float4*)(row + i);
        *(float4*)(srow + i) = v;
        m = fmaxf(m, fmaxf(fmaxf(v.x, v.y), fmaxf(v.z, v.w)));
    }
#pragma unroll
    for (int o = 16; o; o >>= 1) m = fmaxf(m, __shfl_xor_sync(0xffffffffu, m, o));
    if (l == 0) red[w] = m;
    __syncthreads();
    if (w == 0) {
        float t = (l < 8) ? red[l] : -3.402823466e+38f;
#pragma unroll
        for (int o = 16; o; o >>= 1) t = fmaxf(t, __shfl_xor_sync(0xffffffffu, t, o));
        if (l == 0) red[0] = t;
    }
    __syncthreads();
    const float M = red[0];

    float s = 0.f;
#pragma unroll
    for (int r = 0; r < 2; r++) {
        const int i = (threadIdx.x + (r << 8)) << 2;
        float4 v = *(float4*)(srow + i);
        v.x = __expf(v.x - M);
        v.y = __expf(v.y - M);
        v.z = __expf(v.z - M);
        v.w = __expf(v.w - M);
        *(float4*)(srow + i) = v;
        s += (v.x + v.y) + (v.z + v.w);
    }
#pragma unroll
    for (int o = 16; o; o >>= 1) s += __shfl_xor_sync(0xffffffffu, s, o);
    if (l == 0) red[w] = s;
    __syncthreads();
    if (w == 0) {
        float t = (l < 8) ? red[l] : 0.f;
#pragma unroll
        for (int o = 16; o; o >>= 1) t += __shfl_xor_sync(0xffffffffu, t, o);
        if (l == 0) red[0] = t;
    }
    __syncthreads();
    const float inv = 1.0f / red[0];

#pragma unroll
    for (int r = 0; r < 2; r++) {
        const int i = (threadIdx.x + (r << 8)) << 2;
        float4 v = *(float4*)(srow + i);
        h16 h0,h1,h2,h3,l0,l1,l2,l3;
        split2h(v.x * inv, h0, l0);
        split2h(v.y * inv, h1, l1);
        split2h(v.z * inv, h2, l2);
        split2h(v.w * inv, h3, l3);
        *(half2*)(hrow + i)     = __halves2half2(h0, h1);
        *(half2*)(hrow + i + 2) = __halves2half2(h2, h3);
        *(half2*)(lrow + i)     = __halves2half2(l0, l1);
        *(half2*)(lrow + i + 2) = __halves2half2(l2, l3);
    }
}

// ---------------------------------------------------------------------------
static inline int split_grid(long long n)
{
    long long b = (n / 4 + 255) / 256;
    if (b > 8192) b = 8192;
    return (int)b;
}

extern "C" void kernel_launch(void* const* d_in, const int* in_sizes, int n_in,
                              void* d_out, int out_size)
{
    const float* X     = (const float*)d_in[0];
    const float* W_dq  = (const float*)d_in[1];
    const float* gq    = (const float*)d_in[2];
    const float* W_uq  = (const float*)d_in[3];
    const float* W_dkv = (const float*)d_in[4];
    const float* gkv   = (const float*)d_in[5];
    const float* W_ukv = (const float*)d_in[6];
    const float* W_o   = (const float*)d_in[7];
    float* out = (float*)d_out;

    float *cq, *qcr, *ckv, *sc;
    h16 *Xh,*Xl,*Wdq,*Wuq,*Wdkv,*Wukv,*Wo;
    h16 *cqh,*cql,*qh,*ql,*ckvnh,*ckvnl,*krh,*kvh,*kTh,*Ph,*Pl,*oh,*ol;

    cudaGetSymbolAddress((void**)&cq,  g_cq);
    cudaGetSymbolAddress((void**)&qcr, g_qcr);
    cudaGetSymbolAddress((void**)&ckv, g_ckv);
    cudaGetSymbolAddress((void**)&sc,  g_sc);
    cudaGetSymbolAddress((void**)&Xh,  g_Xh);   cudaGetSymbolAddress((void**)&Xl,  g_Xl);
    cudaGetSymbolAddress((void**)&Wdq,  g_Wdq);
    cudaGetSymbolAddress((void**)&Wuq,  g_Wuq);
    cudaGetSymbolAddress((void**)&Wdkv, g_Wdkv);
    cudaGetSymbolAddress((void**)&Wukv, g_Wukv);
    cudaGetSymbolAddress((void**)&Wo,   g_Wo);
    cudaGetSymbolAddress((void**)&cqh, g_cqh);   cudaGetSymbolAddress((void**)&cql, g_cql);
    cudaGetSymbolAddress((void**)&qh,  g_qh);    cudaGetSymbolAddress((void**)&ql,  g_ql);
    cudaGetSymbolAddress((void**)&ckvnh, g_ckvnh); cudaGetSymbolAddress((void**)&ckvnl, g_ckvnl);
    cudaGetSymbolAddress((void**)&krh, g_krh);
    cudaGetSymbolAddress((void**)&kvh, g_kvh);
    cudaGetSymbolAddress((void**)&kTh, g_kTh);
    cudaGetSymbolAddress((void**)&Ph,  g_Ph);    cudaGetSymbolAddress((void**)&Pl,  g_Pl);
    cudaGetSymbolAddress((void**)&oh,  g_oh);    cudaGetSymbolAddress((void**)&ol,  g_ol);

    cudaFuncSetAttribute(bgemm2, cudaFuncAttributeMaxDynamicSharedMemorySize, SMEM_BYTES);

    dim3 blk(256);
    const int SB = SMEM_BYTES;

    // ---- prepare operands ----
    long long nX = (long long)S_LEN * HIDDEN;
    split16_kernel<<<split_grid(nX), blk>>>(X, Xh, Xl, nX);
    quant16_kernel<<<split_grid((long long)HIDDEN * DQ), blk>>>(W_dq, Wdq, (long long)HIDDEN * DQ);
    quant16_kernel<<<split_grid((long long)DQ * NQCR), blk>>>(W_uq, Wuq, (long long)DQ * NQCR);
    quant16_kernel<<<split_grid((long long)HIDDEN * DCKV), blk>>>(W_dkv, Wdkv, (long long)HIDDEN * DCKV);
    quant16_kernel<<<split_grid((long long)DKV * NKV), blk>>>(W_ukv, Wukv, (long long)DKV * NKV);
    quant16_kernel<<<split_grid((long long)NODIM * HIDDEN), blk>>>(W_o, Wo, (long long)NODIM * HIDDEN);

    // ---- G1: c_q = X @ W_dq ----
    bgemm2<<<dim3(DQ / 128, S_LEN / 128, 1), blk, SB>>>(
        S_LEN, DQ, HIDDEN, Xh, Xl, HIDDEN, 0, Wdq, DQ, 0,
        cq, (h16*)0, (h16*)0, DQ, 0, 1.f);

    rmsnorm_split_kernel<<<S_LEN, 256>>>(cq, gq, DQ, DQ, DQ, cqh, cql);

    // ---- G2: qcr = rmsnorm(c_q) @ W_uq ----
    bgemm2<<<dim3(NQCR / 128, S_LEN / 128, 1), blk, SB>>>(
        S_LEN, NQCR, DQ, cqh, cql, DQ, 0, Wuq, NQCR, 0,
        qcr, (h16*)0, (h16*)0, NQCR, 0, 1.f);

    rope_q_kernel<<<(S_LEN * NH) / 8, 256>>>(qcr);
    long long nq = (long long)S_LEN * NQCR;
    split16_kernel<<<split_grid(nq), blk>>>(qcr, qh, ql, nq);

    // ---- G3: ckv_kr = X @ W_dkv ----
    bgemm2<<<dim3((DCKV + 127) / 128, S_LEN / 128, 1), blk, SB>>>(
        S_LEN, DCKV, HIDDEN, Xh, Xl, HIDDEN, 0, Wdkv, DCKV, 0,
        ckv, (h16*)0, (h16*)0, DCKV, 0, 1.f);

    rmsnorm_split_kernel<<<S_LEN, 256>>>(ckv, gkv, DKV, DCKV, DKV, ckvnh, ckvnl);
    rope_k_kernel<<<S_LEN / 8, 256>>>(ckv, krh);

    // ---- G4: kv = rmsnorm(c_kv) @ W_ukv (single fp16 out) ----
    bgemm2<<<dim3(NKV / 128, S_LEN / 128, 1), blk, SB>>>(
        S_LEN, NKV, DKV, ckvnh, ckvnl, DKV, 0, Wukv, NKV, 0,
        (float*)0, kvh, (h16*)0, NKV, 0, 1.f);

    build_kT_kernel<<<4096, 256>>>(kvh, krh, kTh);

    // ---- G5: scores[h] = Q[h] @ K[h]^T * scale ----
    float scale = 1.0f / sqrtf((float)DQR);
    bgemm2<<<dim3(S_LEN / 128, S_LEN / 128, NH), blk, SB>>>(
        S_LEN, S_LEN, DQR,
        qh, ql, NQCR, (long long)DQR,
        kTh, S_LEN, (long long)DQR * S_LEN,
        sc, (h16*)0, (h16*)0, S_LEN, (long long)S_LEN * S_LEN, scale);

    softmax_fused_kernel<<<NH * S_LEN, 256>>>(sc, Ph, Pl);

    // ---- G6: O[h] = P[h] @ V[h] (fp16 hi/lo out) ----
    bgemm2<<<dim3(1, S_LEN / 128, NH), blk, SB>>>(
        S_LEN, DH, S_LEN,
        Ph, Pl, S_LEN, (long long)S_LEN * S_LEN,
        kvh + DH, NKV, (long long)2 * DH,
        (float*)0, oh, ol, NODIM, (long long)DH, 1.f);

    // ---- G7: out = O @ W_o ----
    bgemm2<<<dim3(HIDDEN / 128, S_LEN / 128, 1), blk, SB>>>(
        S_LEN, HIDDEN, NODIM, oh, ol, NODIM, 0, Wo, HIDDEN, 0,
        out, (h16*)0, (h16*)0, HIDDEN, 0, 1.f);
}

// round 14
// speedup vs baseline: 2.3782x; 1.2716x over previous
#include <cuda_runtime.h>
#include <cuda_fp16.h>
#include <math.h>
#include <stdint.h>
#include <cstdint>

// ---------------------------------------------------------------------------
// MLA forward — fp16 A-split GEMMs (C = Ah·B [+ Al·B], B single fp16)
// via mma.sync m16n8k16.f16 + cp.async 3-stage pipeline + ldmatrix.
// Q and P use single-pass A (quant error ~1.2e-4 each, inside budget).
// Shapes: B=1, S=2048, HIDDEN=7168, NH=32, DQ=1536, DKV=512, DH=128, DR=64
// ---------------------------------------------------------------------------

#define S_LEN   2048
#define HIDDEN  7168
#define NH      32
#define DQ      1536
#define DKV     512
#define DH      128
#define DR      64
#define DQR     (DH + DR)            // 192
#define NQCR    (NH * DQR)           // 6144
#define NKV     (NH * 2 * DH)        // 8192
#define DCKV    (DKV + DR)           // 576
#define NODIM   (NH * DH)            // 4096

typedef __half h16;

// ---------------- scratch (device globals; no allocation allowed) ----------
__device__ float g_cq [(long long)S_LEN * DQ];
__device__ float g_qcr[(long long)S_LEN * NQCR];
__device__ float g_ckv[(long long)S_LEN * DCKV];
__device__ float g_sc [(long long)NH * S_LEN * S_LEN];

__device__ h16 g_Xh [(long long)S_LEN * HIDDEN],  g_Xl [(long long)S_LEN * HIDDEN];
__device__ h16 g_Wdq [(long long)HIDDEN * DQ];          // B-side: single fp16
__device__ h16 g_Wuq [(long long)DQ * NQCR];
__device__ h16 g_Wdkv[(long long)HIDDEN * DCKV];
__device__ h16 g_Wukv[(long long)DKV * NKV];
__device__ h16 g_Wo  [(long long)NODIM * HIDDEN];
__device__ h16 g_cqh [(long long)S_LEN * DQ],     g_cql [(long long)S_LEN * DQ];
__device__ h16 g_qh  [(long long)S_LEN * NQCR];         // Q single fp16
__device__ h16 g_ckvnh[(long long)S_LEN * DKV],   g_ckvnl[(long long)S_LEN * DKV];
__device__ h16 g_krh [(long long)S_LEN * DR];           // roped k_r, single
__device__ h16 g_kvh [(long long)S_LEN * NKV];          // kv, single (B-side)
__device__ h16 g_kTh [(long long)NH * DQR * S_LEN];     // K^T, single (B-side)
__device__ h16 g_Ph  [(long long)NH * S_LEN * S_LEN];   // P single fp16
__device__ h16 g_oh  [(long long)S_LEN * NODIM],  g_ol [(long long)S_LEN * NODIM];

// ---------------------------------------------------------------------------
__device__ __forceinline__ void split2h(float v, h16& h, h16& l)
{
    h16 hh = __float2half_rn(v);
    h = hh;
    l = __float2half_rn(v - __half2float(hh));
}

// fp32 -> fp16 hi/lo split. n % 4 == 0.
__global__ void split16_kernel(const float* __restrict__ s,
                               h16* __restrict__ h, h16* __restrict__ l,
                               long long n)
{
    for (long long i = ((long long)blockIdx.x * blockDim.x + threadIdx.x) * 4;
         i < n; i += (long long)gridDim.x * blockDim.x * 4) {
        float4 v = *(const float4*)(s + i);
        h16 h0,h1,h2,h3,l0,l1,l2,l3;
        split2h(v.x,h0,l0); split2h(v.y,h1,l1); split2h(v.z,h2,l2); split2h(v.w,h3,l3);
        *(half2*)(h + i)     = __halves2half2(h0, h1);
        *(half2*)(h + i + 2) = __halves2half2(h2, h3);
        *(half2*)(l + i)     = __halves2half2(l0, l1);
        *(half2*)(l + i + 2) = __halves2half2(l2, l3);
    }
}

// fp32 -> fp16 single quantize. n % 4 == 0.
__global__ void quant16_kernel(const float* __restrict__ s,
                               h16* __restrict__ h, long long n)
{
    for (long long i = ((long long)blockIdx.x * blockDim.x + threadIdx.x) * 4;
         i < n; i += (long long)gridDim.x * blockDim.x * 4) {
        float4 v = *(const float4*)(s + i);
        *(half2*)(h + i)     = __halves2half2(__float2half_rn(v.x), __float2half_rn(v.y));
        *(half2*)(h + i + 2) = __halves2half2(__float2half_rn(v.z), __float2half_rn(v.w));
    }
}

// ---------------------------------------------------------------------------
#define MMA_OP(ac, a, b)                                                     \
    asm volatile("mma.sync.aligned.m16n8k16.row.col.f32.f16.f16.f32 "        \
        "{%0,%1,%2,%3}, {%4,%5,%6,%7}, {%8,%9}, {%0,%1,%2,%3};"              \
        : "+f"((ac)[0]), "+f"((ac)[1]), "+f"((ac)[2]), "+f"((ac)[3])         \
        : "r"((a)[0]), "r"((a)[1]), "r"((a)[2]), "r"((a)[3]),                \
          "r"((b)[0]), "r"((b)[1]))

#define CP16(dst, src) \
    asm volatile("cp.async.cg.shared.global [%0], [%1], 16;" :: "r"(dst), "l"(src))
#define CP_COMMIT() asm volatile("cp.async.commit_group;")
#define CP_WAIT1()  asm volatile("cp.async.wait_group 1;")

#define LDSM_X4(f, addr)                                                      \
    asm volatile("ldmatrix.sync.aligned.m8n8.x4.shared.b16 {%0,%1,%2,%3}, [%4];" \
        : "=r"((f)[0]), "=r"((f)[1]), "=r"((f)[2]), "=r"((f)[3]) : "r"(addr))
#define LDSM_X4T(r0, r1, r2, r3, addr)                                        \
    asm volatile("ldmatrix.sync.aligned.m8n8.x4.trans.shared.b16 {%0,%1,%2,%3}, [%4];" \
        : "=r"(r0), "=r"(r1), "=r"(r2), "=r"(r3) : "r"(addr))

// ---------------------------------------------------------------------------
// GEMM, fp16 A-split: C = alpha * (Ah·B [+ Al·B]). B single fp16.
// Al == nullptr -> single-pass A (half the mma work & A traffic).
// 128x128 tile, BK=32, 3-stage cp.async, 256 threads, 8 warps of 32x64.
// A [M][K] k-contig. B [K][N] n-contig.
// Outputs: fp32 C and/or fp16 Ch (+ optional Cl hi/lo pair).
// M%128==0, K%32==0, N%8==0 effective (clamped loads), lda/ldb%8==0.
// ---------------------------------------------------------------------------
#define A_ST  (128 * 40)
#define B_ST  (32 * 136)
#define STG   (2 * A_ST + B_ST)               // 14592 elems
#define SMEM_BYTES (3 * STG * 2)              // 87552 bytes

__global__ __launch_bounds__(256, 1)
void bgemm2(int M, int N, int K,
            const h16* __restrict__ Ah, const h16* __restrict__ Al,
            int lda, long long sA,
            const h16* __restrict__ B, int ldb, long long sB,
            float* __restrict__ C, h16* __restrict__ Ch, h16* __restrict__ Cl,
            int ldc, long long sC, float alpha)
{
    extern __shared__ __align__(16) char dynsmem[];
    uint32_t sbase = (uint32_t)__cvta_generic_to_shared(dynsmem);

    const bool hasL = (Al != (const h16*)0);

    const h16* pAh = Ah + (long long)blockIdx.z * sA;
    const h16* pAl = hasL ? Al + (long long)blockIdx.z * sA : (const h16*)0;
    const h16* pB  = B  + (long long)blockIdx.z * sB;

    const int tid = threadIdx.x;
    const int bm = blockIdx.y << 7;
    const int bn = blockIdx.x << 7;

    const int lane = tid & 31;
    const int warp = tid >> 5;
    const int wm = (warp & 3) << 5;
    const int wn = (warp >> 2) << 6;
    const int g  = lane >> 2;
    const int qt = (lane & 3) << 1;

    const int nk = K >> 5;

    float acc[2][8][4];
#pragma unroll
    for (int i = 0; i < 2; i++)
#pragma unroll
        for (int j = 0; j < 8; j++)
#pragma unroll
            for (int c = 0; c < 4; c++) acc[i][j][c] = 0.f;

    auto issue_stage = [&](int stg, int k0) {
        uint32_t sb = sbase + (uint32_t)(stg * STG * 2);
#pragma unroll
        for (int r = 0; r < 2; r++) {
            const int c = tid + (r << 8);
            // A: row = c/4, k-chunk = (c%4)*8
            const int arow = c >> 2;
            const int ak   = (c & 3) << 3;
            const long long aoff = (long long)(bm + arow) * lda + k0 + ak;
            const uint32_t dA = sb + (uint32_t)((arow * 40 + ak) * 2);
            CP16(dA, pAh + aoff);
            if (hasL) CP16(dA + A_ST * 2, pAl + aoff);
            // B single: k-row = c/16, n-chunk = (c%16)*8
            const int krow = c >> 4;
            const int nc   = (c & 15) << 3;
            int gn = bn + nc;
            if (gn > N - 8) gn = N - 8;
            const long long boff = (long long)(k0 + krow) * ldb + gn;
            const uint32_t dB = sb + (uint32_t)((2 * A_ST + krow * 136 + nc) * 2);
            CP16(dB, pB + boff);
        }
    };

    issue_stage(0, 0);
    CP_COMMIT();
    if (nk > 1) issue_stage(1, 32);
    CP_COMMIT();

    const int ar  = lane & 15;
    const int hi8 = (lane & 16) >> 1;

    for (int kt = 0; kt < nk; kt++) {
        CP_WAIT1();
        __syncthreads();

        if (kt + 2 < nk) issue_stage((kt + 2) % 3, (kt + 2) << 5);
        CP_COMMIT();

        const uint32_t sb = sbase + (uint32_t)((kt % 3) * STG * 2);
        const uint32_t aH = sb;
        const uint32_t aL = sb + A_ST * 2;
        const uint32_t bB = sb + 2 * A_ST * 2;

#pragma unroll
        for (int ks = 0; ks < 2; ks++) {
            const int ka = (ks << 4) + hi8;
            const uint32_t adr0 = aH + (uint32_t)(((wm + ar) * 40 + ka) * 2);
            uint32_t afH0[4], afH1[4];
            LDSM_X4(afH0, adr0);
            LDSM_X4(afH1, adr0 + 16 * 80);

            const int kb = (ks << 4) + ar;
            const uint32_t bdr = bB + (uint32_t)((kb * 136 + wn + hi8) * 2);
            uint32_t bf[8][2];
#pragma unroll
            for (int jp = 0; jp < 4; jp++)
                LDSM_X4T(bf[2*jp][0], bf[2*jp][1], bf[2*jp+1][0], bf[2*jp+1][1],
                         bdr + jp * 32);

            // pass 1: Ah * B
#pragma unroll
            for (int jn = 0; jn < 8; jn++) {
                MMA_OP(acc[0][jn], afH0, bf[jn]);
                MMA_OP(acc[1][jn], afH1, bf[jn]);
            }

            // pass 2: Al * B (B fragments reused)
            if (hasL) {
                const uint32_t adrL = aL + (uint32_t)(((wm + ar) * 40 + ka) * 2);
                uint32_t afL0[4], afL1[4];
                LDSM_X4(afL0, adrL);
                LDSM_X4(afL1, adrL + 16 * 80);
#pragma unroll
                for (int jn = 0; jn < 8; jn++) {
                    MMA_OP(acc[0][jn], afL0, bf[jn]);
                    MMA_OP(acc[1][jn], afL1, bf[jn]);
                }
            }
        }
    }

    float* pC = C ? C + (long long)blockIdx.z * sC : (float*)0;
    h16* pCh = Ch ? Ch + (long long)blockIdx.z * sC : (h16*)0;
    h16* pCl = Cl ? Cl + (long long)blockIdx.z * sC : (h16*)0;

#pragma unroll
    for (int im = 0; im < 2; im++) {
#pragma unroll
        for (int jn = 0; jn < 8; jn++) {
            const int row = bm + wm + (im << 4) + g;
            const int col = bn + wn + (jn << 3) + qt;
            if (col < N) {
                const float v0 = alpha * acc[im][jn][0];
                const float v1 = alpha * acc[im][jn][1];
                const float v2 = alpha * acc[im][jn][2];
                const float v3 = alpha * acc[im][jn][3];
                if (pC) {
                    *(float2*)(pC + (long long)row * ldc + col) = make_float2(v0, v1);
                    *(float2*)(pC + (long long)(row + 8) * ldc + col) = make_float2(v2, v3);
                }
                if (pCh && pCl) {
                    h16 h0,h1,h2,h3,l0,l1,l2,l3;
                    split2h(v0,h0,l0); split2h(v1,h1,l1);
                    split2h(v2,h2,l2); split2h(v3,h3,l3);
                    *(half2*)(pCh + (long long)row * ldc + col) = __halves2half2(h0, h1);
                    *(half2*)(pCl + (long long)row * ldc + col) = __halves2half2(l0, l1);
                    *(half2*)(pCh + (long long)(row + 8) * ldc + col) = __halves2half2(h2, h3);
                    *(half2*)(pCl + (long long)(row + 8) * ldc + col) = __halves2half2(l2, l3);
                } else if (pCh) {
                    *(half2*)(pCh + (long long)row * ldc + col) =
                        __halves2half2(__float2half_rn(v0), __float2half_rn(v1));
                    *(half2*)(pCh + (long long)(row + 8) * ldc + col) =
                        __halves2half2(__float2half_rn(v2), __float2half_rn(v3));
                }
            }
        }
    }
}

// ---------------------------------------------------------------------------
// RMSNorm over first W cols (row stride ld in, ldo out), fp16 hi/lo out.
// ---------------------------------------------------------------------------
__global__ void rmsnorm_split_kernel(const float* __restrict__ x,
                                     const float* __restrict__ g,
                                     int W, int ld, int ldo,
                                     h16* __restrict__ oh, h16* __restrict__ ol)
{
    __shared__ float red[32];
    const float* row = x + (long long)blockIdx.x * ld;
    float s = 0.f;
    for (int i = threadIdx.x; i < W; i += blockDim.x) {
        float v = row[i];
        s += v * v;
    }
#pragma unroll
    for (int o = 16; o; o >>= 1) s += __shfl_xor_sync(0xffffffffu, s, o);
    int w = threadIdx.x >> 5, l = threadIdx.x & 31;
    if (l == 0) red[w] = s;
    __syncthreads();
    if (w == 0) {
        float t = (l < (blockDim.x >> 5)) ? red[l] : 0.f;
#pragma unroll
        for (int o = 16; o; o >>= 1) t += __shfl_xor_sync(0xffffffffu, t, o);
        if (l == 0) red[0] = t;
    }
    __syncthreads();
    float scale = rsqrtf(red[0] / (float)W + 1.1920929e-07f);
    h16* ohr = oh + (long long)blockIdx.x * ldo;
    h16* olr = ol + (long long)blockIdx.x * ldo;
    for (int i = threadIdx.x; i < W; i += blockDim.x) {
        h16 hh, ll;
        split2h(row[i] * scale * g[i], hh, ll);
        ohr[i] = hh;
        olr[i] = ll;
    }
}

// ---------------------------------------------------------------------------
// RoPE (D=64)
// ---------------------------------------------------------------------------
__device__ __forceinline__ void rope_pair(float* base, int j, int t)
{
    float ex  = (2.0f * (float)j) / 64.0f;
    float inv = 1.0f / powf(10000.0f, ex);
    float fr  = (float)t * inv;
    float c   = cosf(fr);
    float sn  = sinf(fr);
    float x1 = base[j];
    float x2 = base[j + 32];
    base[j]      = x1 * c - x2 * sn;
    base[j + 32] = x2 * c + x1 * sn;
}

__global__ void rope_q_kernel(float* __restrict__ qcr)
{
    int item = blockIdx.x * (blockDim.x >> 5) + (threadIdx.x >> 5);
    if (item >= S_LEN * NH) return;
    int s = item >> 5;
    int h = item & 31;
    int j = threadIdx.x & 31;
    rope_pair(qcr + (long long)s * NQCR + h * DQR + DH, j, s);
}

// rope on ckv cols 512..575, write single fp16 k_r
__global__ void rope_k_kernel(float* __restrict__ ckv, h16* __restrict__ krh)
{
    int item = blockIdx.x * (blockDim.x >> 5) + (threadIdx.x >> 5);
    if (item >= S_LEN) return;
    int j = threadIdx.x & 31;
    float* base = ckv + (long long)item * DCKV + DKV;
    rope_pair(base, j, item);
    krh[(long long)item * DR + j]      = __float2half_rn(base[j]);
    krh[(long long)item * DR + j + 32] = __float2half_rn(base[j + 32]);
}

// ---------------------------------------------------------------------------
// kT[h][d][s] single fp16 from kv fp16 + roped k_r fp16.
// ---------------------------------------------------------------------------
__global__ void build_kT_kernel(const h16* __restrict__ kvh,
                                const h16* __restrict__ krh,
                                h16* __restrict__ kTh)
{
    const long long total = (long long)NH * DQR * S_LEN;
    for (long long i = (long long)blockIdx.x * blockDim.x + threadIdx.x;
         i < total; i += (long long)gridDim.x * blockDim.x) {
        int s = (int)(i % S_LEN);
        long long t = i / S_LEN;
        int d = (int)(t % DQR);
        int h = (int)(t / DQR);
        kTh[i] = (d < DH) ? kvh[(long long)s * NKV + h * 2 * DH + d]
                          : krh[(long long)s * DR + (d - DH)];
    }
}

// ---------------------------------------------------------------------------
// Single-pass smem softmax (width 2048), single fp16 P output.
// ---------------------------------------------------------------------------
__global__ __launch_bounds__(256)
void softmax_fused_kernel(const float* __restrict__ sc, h16* __restrict__ ph)
{
    __shared__ float srow[S_LEN];
    __shared__ float red[32];
    const float* row = sc + (long long)blockIdx.x * S_LEN;
    h16* hrow = ph + (long long)blockIdx.x * S_LEN;
    const int w = threadIdx.x >> 5, l = threadIdx.x & 31;

    float m = -3.402823466e+38f;
#pragma unroll
    for (int r = 0; r < 2; r++) {
        const int i = (threadIdx.x + (r << 8)) << 2;
        float4 v = *(const float4*)(row + i);
        *(float4*)(srow + i) = v;
        m = fmaxf(m, fmaxf(fmaxf(v.x, v.y), fmaxf(v.z, v.w)));
    }
#pragma unroll
    for (int o = 16; o; o >>= 1) m = fmaxf(m, __shfl_xor_sync(0xffffffffu, m, o));
    if (l == 0) red[w] = m;
    __syncthreads();
    if (w == 0) {
        float t = (l < 8) ? red[l] : -3.402823466e+38f;
#pragma unroll
        for (int o = 16; o; o >>= 1) t = fmaxf(t, __shfl_xor_sync(0xffffffffu, t, o));
        if (l == 0) red[0] = t;
    }
    __syncthreads();
    const float M = red[0];

    float s = 0.f;
#pragma unroll
    for (int r = 0; r < 2; r++) {
        const int i = (threadIdx.x + (r << 8)) << 2;
        float4 v = *(float4*)(srow + i);
        v.x = __expf(v.x - M);
        v.y = __expf(v.y - M);
        v.z = __expf(v.z - M);
        v.w = __expf(v.w - M);
        *(float4*)(srow + i) = v;
        s += (v.x + v.y) + (v.z + v.w);
    }
#pragma unroll
    for (int o = 16; o; o >>= 1) s += __shfl_xor_sync(0xffffffffu, s, o);
    if (l == 0) red[w] = s;
    __syncthreads();
    if (w == 0) {
        float t = (l < 8) ? red[l] : 0.f;
#pragma unroll
        for (int o = 16; o; o >>= 1) t += __shfl_xor_sync(0xffffffffu, t, o);
        if (l == 0) red[0] = t;
    }
    __syncthreads();
    const float inv = 1.0f / red[0];

#pragma unroll
    for (int r = 0; r < 2; r++) {
        const int i = (threadIdx.x + (r << 8)) << 2;
        float4 v = *(float4*)(srow + i);
        *(half2*)(hrow + i) =
            __halves2half2(__float2half_rn(v.x * inv), __float2half_rn(v.y * inv));
        *(half2*)(hrow + i + 2) =
            __halves2half2(__float2half_rn(v.z * inv), __float2half_rn(v.w * inv));
    }
}

// ---------------------------------------------------------------------------
static inline int split_grid(long long n)
{
    long long b = (n / 4 + 255) / 256;
    if (b > 8192) b = 8192;
    return (int)b;
}

extern "C" void kernel_launch(void* const* d_in, const int* in_sizes, int n_in,
                              void* d_out, int out_size)
{
    const float* X     = (const float*)d_in[0];
    const float* W_dq  = (const float*)d_in[1];
    const float* gq    = (const float*)d_in[2];
    const float* W_uq  = (const float*)d_in[3];
    const float* W_dkv = (const float*)d_in[4];
    const float* gkv   = (const float*)d_in[5];
    const float* W_ukv = (const float*)d_in[6];
    const float* W_o   = (const float*)d_in[7];
    float* out = (float*)d_out;

    float *cq, *qcr, *ckv, *sc;
    h16 *Xh,*Xl,*Wdq,*Wuq,*Wdkv,*Wukv,*Wo;
    h16 *cqh,*cql,*qh,*ckvnh,*ckvnl,*krh,*kvh,*kTh,*Ph,*oh,*ol;

    cudaGetSymbolAddress((void**)&cq,  g_cq);
    cudaGetSymbolAddress((void**)&qcr, g_qcr);
    cudaGetSymbolAddress((void**)&ckv, g_ckv);
    cudaGetSymbolAddress((void**)&sc,  g_sc);
    cudaGetSymbolAddress((void**)&Xh,  g_Xh);   cudaGetSymbolAddress((void**)&Xl,  g_Xl);
    cudaGetSymbolAddress((void**)&Wdq,  g_Wdq);
    cudaGetSymbolAddress((void**)&Wuq,  g_Wuq);
    cudaGetSymbolAddress((void**)&Wdkv, g_Wdkv);
    cudaGetSymbolAddress((void**)&Wukv, g_Wukv);
    cudaGetSymbolAddress((void**)&Wo,   g_Wo);
    cudaGetSymbolAddress((void**)&cqh, g_cqh);   cudaGetSymbolAddress((void**)&cql, g_cql);
    cudaGetSymbolAddress((void**)&qh,  g_qh);
    cudaGetSymbolAddress((void**)&ckvnh, g_ckvnh); cudaGetSymbolAddress((void**)&ckvnl, g_ckvnl);
    cudaGetSymbolAddress((void**)&krh, g_krh);
    cudaGetSymbolAddress((void**)&kvh, g_kvh);
    cudaGetSymbolAddress((void**)&kTh, g_kTh);
    cudaGetSymbolAddress((void**)&Ph,  g_Ph);
    cudaGetSymbolAddress((void**)&oh,  g_oh);    cudaGetSymbolAddress((void**)&ol,  g_ol);

    cudaFuncSetAttribute(bgemm2, cudaFuncAttributeMaxDynamicSharedMemorySize, SMEM_BYTES);

    dim3 blk(256);
    const int SB = SMEM_BYTES;

    // ---- prepare operands ----
    long long nX = (long long)S_LEN * HIDDEN;
    split16_kernel<<<split_grid(nX), blk>>>(X, Xh, Xl, nX);
    quant16_kernel<<<split_grid((long long)HIDDEN * DQ), blk>>>(W_dq, Wdq, (long long)HIDDEN * DQ);
    quant16_kernel<<<split_grid((long long)DQ * NQCR), blk>>>(W_uq, Wuq, (long long)DQ * NQCR);
    quant16_kernel<<<split_grid((long long)HIDDEN * DCKV), blk>>>(W_dkv, Wdkv, (long long)HIDDEN * DCKV);
    quant16_kernel<<<split_grid((long long)DKV * NKV), blk>>>(W_ukv, Wukv, (long long)DKV * NKV);
    quant16_kernel<<<split_grid((long long)NODIM * HIDDEN), blk>>>(W_o, Wo, (long long)NODIM * HIDDEN);

    // ---- G1: c_q = X @ W_dq (2-pass A) ----
    bgemm2<<<dim3(DQ / 128, S_LEN / 128, 1), blk, SB>>>(
        S_LEN, DQ, HIDDEN, Xh, Xl, HIDDEN, 0, Wdq, DQ, 0,
        cq, (h16*)0, (h16*)0, DQ, 0, 1.f);

    rmsnorm_split_kernel<<<S_LEN, 256>>>(cq, gq, DQ, DQ, DQ, cqh, cql);

    // ---- G2: qcr = rmsnorm(c_q) @ W_uq (2-pass A) ----
    bgemm2<<<dim3(NQCR / 128, S_LEN / 128, 1), blk, SB>>>(
        S_LEN, NQCR, DQ, cqh, cql, DQ, 0, Wuq, NQCR, 0,
        qcr, (h16*)0, (h16*)0, NQCR, 0, 1.f);

    rope_q_kernel<<<(S_LEN * NH) / 8, 256>>>(qcr);
    // Q single fp16 (quant error ~1.2e-4 on scores — inside budget)
    long long nq = (long long)S_LEN * NQCR;
    quant16_kernel<<<split_grid(nq), blk>>>(qcr, qh, nq);

    // ---- G3: ckv_kr = X @ W_dkv (2-pass A) ----
    bgemm2<<<dim3((DCKV + 127) / 128, S_LEN / 128, 1), blk, SB>>>(
        S_LEN, DCKV, HIDDEN, Xh, Xl, HIDDEN, 0, Wdkv, DCKV, 0,
        ckv, (h16*)0, (h16*)0, DCKV, 0, 1.f);

    rmsnorm_split_kernel<<<S_LEN, 256>>>(ckv, gkv, DKV, DCKV, DKV, ckvnh, ckvnl);
    rope_k_kernel<<<S_LEN / 8, 256>>>(ckv, krh);

    // ---- G4: kv = rmsnorm(c_kv) @ W_ukv (2-pass A, single fp16 out) ----
    bgemm2<<<dim3(NKV / 128, S_LEN / 128, 1), blk, SB>>>(
        S_LEN, NKV, DKV, ckvnh, ckvnl, DKV, 0, Wukv, NKV, 0,
        (float*)0, kvh, (h16*)0, NKV, 0, 1.f);

    build_kT_kernel<<<4096, 256>>>(kvh, krh, kTh);

    // ---- G5: scores[h] = Q[h] @ K[h]^T * scale (single-pass A) ----
    float scale = 1.0f / sqrtf((float)DQR);
    bgemm2<<<dim3(S_LEN / 128, S_LEN / 128, NH), blk, SB>>>(
        S_LEN, S_LEN, DQR,
        qh, (h16*)0, NQCR, (long long)DQR,
        kTh, S_LEN, (long long)DQR * S_LEN,
        sc, (h16*)0, (h16*)0, S_LEN, (long long)S_LEN * S_LEN, scale);

    softmax_fused_kernel<<<NH * S_LEN, 256>>>(sc, Ph);

    // ---- G6: O[h] = P[h] @ V[h] (single-pass A, fp16 hi/lo out) ----
    bgemm2<<<dim3(1, S_LEN / 128, NH), blk, SB>>>(
        S_LEN, DH, S_LEN,
        Ph, (h16*)0, S_LEN, (long long)S_LEN * S_LEN,
        kvh + DH, NKV, (long long)2 * DH,
        (float*)0, oh, ol, NODIM, (long long)DH, 1.f);

    // ---- G7: out = O @ W_o (2-pass A) ----
    bgemm2<<<dim3(HIDDEN / 128, S_LEN / 128, 1), blk, SB>>>(
        S_LEN, HIDDEN, NODIM, oh, ol, NODIM, 0, Wo, HIDDEN, 0,
        out, (h16*)0, (h16*)0, HIDDEN, 0, 1.f);
}

// round 15
// speedup vs baseline: 2.8929x; 1.2164x over previous
#include <cuda_runtime.h>
#include <cuda_fp16.h>
#include <math.h>
#include <stdint.h>
#include <cstdint>

// ---------------------------------------------------------------------------
// MLA forward — fp16 A-split GEMMs (C = Ah·B [+ Al·B], B single fp16)
// via mma.sync m16n8k16.f16 + cp.async 3-stage pipeline + ldmatrix.
// Single-pass A on: Q (G5), P (G6), O (G7), c_qn (G2). 2-pass: X (G1,G3),
// c_kvn (G4). Error model: each single-pass op adds ~1.8e-4 in quadrature.
// Shapes: B=1, S=2048, HIDDEN=7168, NH=32, DQ=1536, DKV=512, DH=128, DR=64
// ---------------------------------------------------------------------------

#define S_LEN   2048
#define HIDDEN  7168
#define NH      32
#define DQ      1536
#define DKV     512
#define DH      128
#define DR      64
#define DQR     (DH + DR)            // 192
#define NQCR    (NH * DQR)           // 6144
#define NKV     (NH * 2 * DH)        // 8192
#define DCKV    (DKV + DR)           // 576
#define NODIM   (NH * DH)            // 4096

typedef __half h16;

// ---------------- scratch (device globals; no allocation allowed) ----------
__device__ float g_cq [(long long)S_LEN * DQ];
__device__ float g_qcr[(long long)S_LEN * NQCR];
__device__ float g_ckv[(long long)S_LEN * DCKV];
__device__ float g_sc [(long long)NH * S_LEN * S_LEN];

__device__ h16 g_Xh [(long long)S_LEN * HIDDEN],  g_Xl [(long long)S_LEN * HIDDEN];
__device__ h16 g_Wdq [(long long)HIDDEN * DQ];          // B-side: single fp16
__device__ h16 g_Wuq [(long long)DQ * NQCR];
__device__ h16 g_Wdkv[(long long)HIDDEN * DCKV];
__device__ h16 g_Wukv[(long long)DKV * NKV];
__device__ h16 g_Wo  [(long long)NODIM * HIDDEN];
__device__ h16 g_cqh [(long long)S_LEN * DQ];           // c_qn single fp16
__device__ h16 g_qh  [(long long)S_LEN * NQCR];         // Q single fp16
__device__ h16 g_ckvnh[(long long)S_LEN * DKV],   g_ckvnl[(long long)S_LEN * DKV];
__device__ h16 g_krh [(long long)S_LEN * DR];           // roped k_r, single
__device__ h16 g_kvh [(long long)S_LEN * NKV];          // kv, single (B-side)
__device__ h16 g_kTh [(long long)NH * DQR * S_LEN];     // K^T, single (B-side)
__device__ h16 g_Ph  [(long long)NH * S_LEN * S_LEN];   // P single fp16
__device__ h16 g_oh  [(long long)S_LEN * NODIM];        // O single fp16

// ---------------------------------------------------------------------------
__device__ __forceinline__ void split2h(float v, h16& h, h16& l)
{
    h16 hh = __float2half_rn(v);
    h = hh;
    l = __float2half_rn(v - __half2float(hh));
}

// fp32 -> fp16 hi/lo split. n % 4 == 0.
__global__ void split16_kernel(const float* __restrict__ s,
                               h16* __restrict__ h, h16* __restrict__ l,
                               long long n)
{
    for (long long i = ((long long)blockIdx.x * blockDim.x + threadIdx.x) * 4;
         i < n; i += (long long)gridDim.x * blockDim.x * 4) {
        float4 v = *(const float4*)(s + i);
        h16 h0,h1,h2,h3,l0,l1,l2,l3;
        split2h(v.x,h0,l0); split2h(v.y,h1,l1); split2h(v.z,h2,l2); split2h(v.w,h3,l3);
        *(half2*)(h + i)     = __halves2half2(h0, h1);
        *(half2*)(h + i + 2) = __halves2half2(h2, h3);
        *(half2*)(l + i)     = __halves2half2(l0, l1);
        *(half2*)(l + i + 2) = __halves2half2(l2, l3);
    }
}

// fp32 -> fp16 single quantize. n % 4 == 0.
__global__ void quant16_kernel(const float* __restrict__ s,
                               h16* __restrict__ h, long long n)
{
    for (long long i = ((long long)blockIdx.x * blockDim.x + threadIdx.x) * 4;
         i < n; i += (long long)gridDim.x * blockDim.x * 4) {
        float4 v = *(const float4*)(s + i);
        *(half2*)(h + i)     = __halves2half2(__float2half_rn(v.x), __float2half_rn(v.y));
        *(half2*)(h + i + 2) = __halves2half2(__float2half_rn(v.z), __float2half_rn(v.w));
    }
}

// ---------------------------------------------------------------------------
#define MMA_OP(ac, a, b)                                                     \
    asm volatile("mma.sync.aligned.m16n8k16.row.col.f32.f16.f16.f32 "        \
        "{%0,%1,%2,%3}, {%4,%5,%6,%7}, {%8,%9}, {%0,%1,%2,%3};"              \
        : "+f"((ac)[0]), "+f"((ac)[1]), "+f"((ac)[2]), "+f"((ac)[3])         \
        : "r"((a)[0]), "r"((a)[1]), "r"((a)[2]), "r"((a)[3]),                \
          "r"((b)[0]), "r"((b)[1]))

#define CP16(dst, src) \
    asm volatile("cp.async.cg.shared.global [%0], [%1], 16;" :: "r"(dst), "l"(src))
#define CP_COMMIT() asm volatile("cp.async.commit_group;")
#define CP_WAIT1()  asm volatile("cp.async.wait_group 1;")

#define LDSM_X4(f, addr)                                                      \
    asm volatile("ldmatrix.sync.aligned.m8n8.x4.shared.b16 {%0,%1,%2,%3}, [%4];" \
        : "=r"((f)[0]), "=r"((f)[1]), "=r"((f)[2]), "=r"((f)[3]) : "r"(addr))
#define LDSM_X4T(r0, r1, r2, r3, addr)                                        \
    asm volatile("ldmatrix.sync.aligned.m8n8.x4.trans.shared.b16 {%0,%1,%2,%3}, [%4];" \
        : "=r"(r0), "=r"(r1), "=r"(r2), "=r"(r3) : "r"(addr))

// ---------------------------------------------------------------------------
// GEMM, fp16 A-split: C = alpha * (Ah·B [+ Al·B]). B single fp16.
// Al == nullptr -> single-pass A (half the mma work & A traffic).
// 128x128 tile, BK=32, 3-stage cp.async, 256 threads, 8 warps of 32x64.
// A [M][K] k-contig. B [K][N] n-contig.
// Outputs: fp32 C and/or fp16 Ch (+ optional Cl hi/lo pair).
// M%128==0, K%32==0, N%8==0 effective (clamped loads), lda/ldb%8==0.
// ---------------------------------------------------------------------------
#define A_ST  (128 * 40)
#define B_ST  (32 * 136)
#define STG   (2 * A_ST + B_ST)               // 14592 elems
#define SMEM_BYTES (3 * STG * 2)              // 87552 bytes

__global__ __launch_bounds__(256, 1)
void bgemm2(int M, int N, int K,
            const h16* __restrict__ Ah, const h16* __restrict__ Al,
            int lda, long long sA,
            const h16* __restrict__ B, int ldb, long long sB,
            float* __restrict__ C, h16* __restrict__ Ch, h16* __restrict__ Cl,
            int ldc, long long sC, float alpha)
{
    extern __shared__ __align__(16) char dynsmem[];
    uint32_t sbase = (uint32_t)__cvta_generic_to_shared(dynsmem);

    const bool hasL = (Al != (const h16*)0);

    const h16* pAh = Ah + (long long)blockIdx.z * sA;
    const h16* pAl = hasL ? Al + (long long)blockIdx.z * sA : (const h16*)0;
    const h16* pB  = B  + (long long)blockIdx.z * sB;

    const int tid = threadIdx.x;
    const int bm = blockIdx.y << 7;
    const int bn = blockIdx.x << 7;

    const int lane = tid & 31;
    const int warp = tid >> 5;
    const int wm = (warp & 3) << 5;
    const int wn = (warp >> 2) << 6;
    const int g  = lane >> 2;
    const int qt = (lane & 3) << 1;

    const int nk = K >> 5;

    float acc[2][8][4];
#pragma unroll
    for (int i = 0; i < 2; i++)
#pragma unroll
        for (int j = 0; j < 8; j++)
#pragma unroll
            for (int c = 0; c < 4; c++) acc[i][j][c] = 0.f;

    auto issue_stage = [&](int stg, int k0) {
        uint32_t sb = sbase + (uint32_t)(stg * STG * 2);
#pragma unroll
        for (int r = 0; r < 2; r++) {
            const int c = tid + (r << 8);
            // A: row = c/4, k-chunk = (c%4)*8
            const int arow = c >> 2;
            const int ak   = (c & 3) << 3;
            const long long aoff = (long long)(bm + arow) * lda + k0 + ak;
            const uint32_t dA = sb + (uint32_t)((arow * 40 + ak) * 2);
            CP16(dA, pAh + aoff);
            if (hasL) CP16(dA + A_ST * 2, pAl + aoff);
            // B single: k-row = c/16, n-chunk = (c%16)*8
            const int krow = c >> 4;
            const int nc   = (c & 15) << 3;
            int gn = bn + nc;
            if (gn > N - 8) gn = N - 8;
            const long long boff = (long long)(k0 + krow) * ldb + gn;
            const uint32_t dB = sb + (uint32_t)((2 * A_ST + krow * 136 + nc) * 2);
            CP16(dB, pB + boff);
        }
    };

    issue_stage(0, 0);
    CP_COMMIT();
    if (nk > 1) issue_stage(1, 32);
    CP_COMMIT();

    const int ar  = lane & 15;
    const int hi8 = (lane & 16) >> 1;

    for (int kt = 0; kt < nk; kt++) {
        CP_WAIT1();
        __syncthreads();

        if (kt + 2 < nk) issue_stage((kt + 2) % 3, (kt + 2) << 5);
        CP_COMMIT();

        const uint32_t sb = sbase + (uint32_t)((kt % 3) * STG * 2);
        const uint32_t aH = sb;
        const uint32_t aL = sb + A_ST * 2;
        const uint32_t bB = sb + 2 * A_ST * 2;

#pragma unroll
        for (int ks = 0; ks < 2; ks++) {
            const int ka = (ks << 4) + hi8;
            const uint32_t adr0 = aH + (uint32_t)(((wm + ar) * 40 + ka) * 2);
            uint32_t afH0[4], afH1[4];
            LDSM_X4(afH0, adr0);
            LDSM_X4(afH1, adr0 + 16 * 80);

            const int kb = (ks << 4) + ar;
            const uint32_t bdr = bB + (uint32_t)((kb * 136 + wn + hi8) * 2);
            uint32_t bf[8][2];
#pragma unroll
            for (int jp = 0; jp < 4; jp++)
                LDSM_X4T(bf[2*jp][0], bf[2*jp][1], bf[2*jp+1][0], bf[2*jp+1][1],
                         bdr + jp * 32);

            // pass 1: Ah * B
#pragma unroll
            for (int jn = 0; jn < 8; jn++) {
                MMA_OP(acc[0][jn], afH0, bf[jn]);
                MMA_OP(acc[1][jn], afH1, bf[jn]);
            }

            // pass 2: Al * B (B fragments reused)
            if (hasL) {
                const uint32_t adrL = aL + (uint32_t)(((wm + ar) * 40 + ka) * 2);
                uint32_t afL0[4], afL1[4];
                LDSM_X4(afL0, adrL);
                LDSM_X4(afL1, adrL + 16 * 80);
#pragma unroll
                for (int jn = 0; jn < 8; jn++) {
                    MMA_OP(acc[0][jn], afL0, bf[jn]);
                    MMA_OP(acc[1][jn], afL1, bf[jn]);
                }
            }
        }
    }

    float* pC = C ? C + (long long)blockIdx.z * sC : (float*)0;
    h16* pCh = Ch ? Ch + (long long)blockIdx.z * sC : (h16*)0;
    h16* pCl = Cl ? Cl + (long long)blockIdx.z * sC : (h16*)0;

#pragma unroll
    for (int im = 0; im < 2; im++) {
#pragma unroll
        for (int jn = 0; jn < 8; jn++) {
            const int row = bm + wm + (im << 4) + g;
            const int col = bn + wn + (jn << 3) + qt;
            if (col < N) {
                const float v0 = alpha * acc[im][jn][0];
                const float v1 = alpha * acc[im][jn][1];
                const float v2 = alpha * acc[im][jn][2];
                const float v3 = alpha * acc[im][jn][3];
                if (pC) {
                    *(float2*)(pC + (long long)row * ldc + col) = make_float2(v0, v1);
                    *(float2*)(pC + (long long)(row + 8) * ldc + col) = make_float2(v2, v3);
                }
                if (pCh && pCl) {
                    h16 h0,h1,h2,h3,l0,l1,l2,l3;
                    split2h(v0,h0,l0); split2h(v1,h1,l1);
                    split2h(v2,h2,l2); split2h(v3,h3,l3);
                    *(half2*)(pCh + (long long)row * ldc + col) = __halves2half2(h0, h1);
                    *(half2*)(pCl + (long long)row * ldc + col) = __halves2half2(l0, l1);
                    *(half2*)(pCh + (long long)(row + 8) * ldc + col) = __halves2half2(h2, h3);
                    *(half2*)(pCl + (long long)(row + 8) * ldc + col) = __halves2half2(l2, l3);
                } else if (pCh) {
                    *(half2*)(pCh + (long long)row * ldc + col) =
                        __halves2half2(__float2half_rn(v0), __float2half_rn(v1));
                    *(half2*)(pCh + (long long)(row + 8) * ldc + col) =
                        __halves2half2(__float2half_rn(v2), __float2half_rn(v3));
                }
            }
        }
    }
}

// ---------------------------------------------------------------------------
// RMSNorm over first W cols (row stride ld in, ldo out).
// ol != nullptr -> hi/lo split out; else single fp16 quant out.
// ---------------------------------------------------------------------------
__global__ void rmsnorm_split_kernel(const float* __restrict__ x,
                                     const float* __restrict__ g,
                                     int W, int ld, int ldo,
                                     h16* __restrict__ oh, h16* __restrict__ ol)
{
    __shared__ float red[32];
    const float* row = x + (long long)blockIdx.x * ld;
    float s = 0.f;
    for (int i = threadIdx.x; i < W; i += blockDim.x) {
        float v = row[i];
        s += v * v;
    }
#pragma unroll
    for (int o = 16; o; o >>= 1) s += __shfl_xor_sync(0xffffffffu, s, o);
    int w = threadIdx.x >> 5, l = threadIdx.x & 31;
    if (l == 0) red[w] = s;
    __syncthreads();
    if (w == 0) {
        float t = (l < (blockDim.x >> 5)) ? red[l] : 0.f;
#pragma unroll
        for (int o = 16; o; o >>= 1) t += __shfl_xor_sync(0xffffffffu, t, o);
        if (l == 0) red[0] = t;
    }
    __syncthreads();
    float scale = rsqrtf(red[0] / (float)W + 1.1920929e-07f);
    h16* ohr = oh + (long long)blockIdx.x * ldo;
    if (ol) {
        h16* olr = ol + (long long)blockIdx.x * ldo;
        for (int i = threadIdx.x; i < W; i += blockDim.x) {
            h16 hh, ll;
            split2h(row[i] * scale * g[i], hh, ll);
            ohr[i] = hh;
            olr[i] = ll;
        }
    } else {
        for (int i = threadIdx.x; i < W; i += blockDim.x)
            ohr[i] = __float2half_rn(row[i] * scale * g[i]);
    }
}

// ---------------------------------------------------------------------------
// RoPE (D=64)
// ---------------------------------------------------------------------------
__device__ __forceinline__ void rope_pair(float* base, int j, int t)
{
    float ex  = (2.0f * (float)j) / 64.0f;
    float inv = 1.0f / powf(10000.0f, ex);
    float fr  = (float)t * inv;
    float c   = cosf(fr);
    float sn  = sinf(fr);
    float x1 = base[j];
    float x2 = base[j + 32];
    base[j]      = x1 * c - x2 * sn;
    base[j + 32] = x2 * c + x1 * sn;
}

__global__ void rope_q_kernel(float* __restrict__ qcr)
{
    int item = blockIdx.x * (blockDim.x >> 5) + (threadIdx.x >> 5);
    if (item >= S_LEN * NH) return;
    int s = item >> 5;
    int h = item & 31;
    int j = threadIdx.x & 31;
    rope_pair(qcr + (long long)s * NQCR + h * DQR + DH, j, s);
}

// rope on ckv cols 512..575, write single fp16 k_r
__global__ void rope_k_kernel(float* __restrict__ ckv, h16* __restrict__ krh)
{
    int item = blockIdx.x * (blockDim.x >> 5) + (threadIdx.x >> 5);
    if (item >= S_LEN) return;
    int j = threadIdx.x & 31;
    float* base = ckv + (long long)item * DCKV + DKV;
    rope_pair(base, j, item);
    krh[(long long)item * DR + j]      = __float2half_rn(base[j]);
    krh[(long long)item * DR + j + 32] = __float2half_rn(base[j + 32]);
}

// ---------------------------------------------------------------------------
// kT[h][d][s] single fp16 from kv fp16 + roped k_r fp16.
// ---------------------------------------------------------------------------
__global__ void build_kT_kernel(const h16* __restrict__ kvh,
                                const h16* __restrict__ krh,
                                h16* __restrict__ kTh)
{
    const long long total = (long long)NH * DQR * S_LEN;
    for (long long i = (long long)blockIdx.x * blockDim.x + threadIdx.x;
         i < total; i += (long long)gridDim.x * blockDim.x) {
        int s = (int)(i % S_LEN);
        long long t = i / S_LEN;
        int d = (int)(t % DQR);
        int h = (int)(t / DQR);
        kTh[i] = (d < DH) ? kvh[(long long)s * NKV + h * 2 * DH + d]
                          : krh[(long long)s * DR + (d - DH)];
    }
}

// ---------------------------------------------------------------------------
// Single-pass smem softmax (width 2048), single fp16 P output.
// ---------------------------------------------------------------------------
__global__ __launch_bounds__(256)
void softmax_fused_kernel(const float* __restrict__ sc, h16* __restrict__ ph)
{
    __shared__ float srow[S_LEN];
    __shared__ float red[32];
    const float* row = sc + (long long)blockIdx.x * S_LEN;
    h16* hrow = ph + (long long)blockIdx.x * S_LEN;
    const int w = threadIdx.x >> 5, l = threadIdx.x & 31;

    float m = -3.402823466e+38f;
#pragma unroll
    for (int r = 0; r < 2; r++) {
        const int i = (threadIdx.x + (r << 8)) << 2;
        float4 v = *(const float4*)(row + i);
        *(float4*)(srow + i) = v;
        m = fmaxf(m, fmaxf(fmaxf(v.x, v.y), fmaxf(v.z, v.w)));
    }
#pragma unroll
    for (int o = 16; o; o >>= 1) m = fmaxf(m, __shfl_xor_sync(0xffffffffu, m, o));
    if (l == 0) red[w] = m;
    __syncthreads();
    if (w == 0) {
        float t = (l < 8) ? red[l] : -3.402823466e+38f;
#pragma unroll
        for (int o = 16; o; o >>= 1) t = fmaxf(t, __shfl_xor_sync(0xffffffffu, t, o));
        if (l == 0) red[0] = t;
    }
    __syncthreads();
    const float M = red[0];

    float s = 0.f;
#pragma unroll
    for (int r = 0; r < 2; r++) {
        const int i = (threadIdx.x + (r << 8)) << 2;
        float4 v = *(float4*)(srow + i);
        v.x = __expf(v.x - M);
        v.y = __expf(v.y - M);
        v.z = __expf(v.z - M);
        v.w = __expf(v.w - M);
        *(float4*)(srow + i) = v;
        s += (v.x + v.y) + (v.z + v.w);
    }
#pragma unroll
    for (int o = 16; o; o >>= 1) s += __shfl_xor_sync(0xffffffffu, s, o);
    if (l == 0) red[w] = s;
    __syncthreads();
    if (w == 0) {
        float t = (l < 8) ? red[l] : 0.f;
#pragma unroll
        for (int o = 16; o; o >>= 1) t += __shfl_xor_sync(0xffffffffu, t, o);
        if (l == 0) red[0] = t;
    }
    __syncthreads();
    const float inv = 1.0f / red[0];

#pragma unroll
    for (int r = 0; r < 2; r++) {
        const int i = (threadIdx.x + (r << 8)) << 2;
        float4 v = *(float4*)(srow + i);
        *(half2*)(hrow + i) =
            __halves2half2(__float2half_rn(v.x * inv), __float2half_rn(v.y * inv));
        *(half2*)(hrow + i + 2) =
            __halves2half2(__float2half_rn(v.z * inv), __float2half_rn(v.w * inv));
    }
}

// ---------------------------------------------------------------------------
static inline int split_grid(long long n)
{
    long long b = (n / 4 + 255) / 256;
    if (b > 8192) b = 8192;
    return (int)b;
}

extern "C" void kernel_launch(void* const* d_in, const int* in_sizes, int n_in,
                              void* d_out, int out_size)
{
    const float* X     = (const float*)d_in[0];
    const float* W_dq  = (const float*)d_in[1];
    const float* gq    = (const float*)d_in[2];
    const float* W_uq  = (const float*)d_in[3];
    const float* W_dkv = (const float*)d_in[4];
    const float* gkv   = (const float*)d_in[5];
    const float* W_ukv = (const float*)d_in[6];
    const float* W_o   = (const float*)d_in[7];
    float* out = (float*)d_out;

    float *cq, *qcr, *ckv, *sc;
    h16 *Xh,*Xl,*Wdq,*Wuq,*Wdkv,*Wukv,*Wo;
    h16 *cqh,*qh,*ckvnh,*ckvnl,*krh,*kvh,*kTh,*Ph,*oh;

    cudaGetSymbolAddress((void**)&cq,  g_cq);
    cudaGetSymbolAddress((void**)&qcr, g_qcr);
    cudaGetSymbolAddress((void**)&ckv, g_ckv);
    cudaGetSymbolAddress((void**)&sc,  g_sc);
    cudaGetSymbolAddress((void**)&Xh,  g_Xh);   cudaGetSymbolAddress((void**)&Xl,  g_Xl);
    cudaGetSymbolAddress((void**)&Wdq,  g_Wdq);
    cudaGetSymbolAddress((void**)&Wuq,  g_Wuq);
    cudaGetSymbolAddress((void**)&Wdkv, g_Wdkv);
    cudaGetSymbolAddress((void**)&Wukv, g_Wukv);
    cudaGetSymbolAddress((void**)&Wo,   g_Wo);
    cudaGetSymbolAddress((void**)&cqh, g_cqh);
    cudaGetSymbolAddress((void**)&qh,  g_qh);
    cudaGetSymbolAddress((void**)&ckvnh, g_ckvnh); cudaGetSymbolAddress((void**)&ckvnl, g_ckvnl);
    cudaGetSymbolAddress((void**)&krh, g_krh);
    cudaGetSymbolAddress((void**)&kvh, g_kvh);
    cudaGetSymbolAddress((void**)&kTh, g_kTh);
    cudaGetSymbolAddress((void**)&Ph,  g_Ph);
    cudaGetSymbolAddress((void**)&oh,  g_oh);

    cudaFuncSetAttribute(bgemm2, cudaFuncAttributeMaxDynamicSharedMemorySize, SMEM_BYTES);

    dim3 blk(256);
    const int SB = SMEM_BYTES;

    // ---- prepare operands ----
    long long nX = (long long)S_LEN * HIDDEN;
    split16_kernel<<<split_grid(nX), blk>>>(X, Xh, Xl, nX);
    quant16_kernel<<<split_grid((long long)HIDDEN * DQ), blk>>>(W_dq, Wdq, (long long)HIDDEN * DQ);
    quant16_kernel<<<split_grid((long long)DQ * NQCR), blk>>>(W_uq, Wuq, (long long)DQ * NQCR);
    quant16_kernel<<<split_grid((long long)HIDDEN * DCKV), blk>>>(W_dkv, Wdkv, (long long)HIDDEN * DCKV);
    quant16_kernel<<<split_grid((long long)DKV * NKV), blk>>>(W_ukv, Wukv, (long long)DKV * NKV);
    quant16_kernel<<<split_grid((long long)NODIM * HIDDEN), blk>>>(W_o, Wo, (long long)NODIM * HIDDEN);

    // ---- G1: c_q = X @ W_dq (2-pass A) ----
    bgemm2<<<dim3(DQ / 128, S_LEN / 128, 1), blk, SB>>>(
        S_LEN, DQ, HIDDEN, Xh, Xl, HIDDEN, 0, Wdq, DQ, 0,
        cq, (h16*)0, (h16*)0, DQ, 0, 1.f);

    // rmsnorm -> single fp16 c_qn
    rmsnorm_split_kernel<<<S_LEN, 256>>>(cq, gq, DQ, DQ, DQ, cqh, (h16*)0);

    // ---- G2: qcr = c_qn @ W_uq (single-pass A) ----
    bgemm2<<<dim3(NQCR / 128, S_LEN / 128, 1), blk, SB>>>(
        S_LEN, NQCR, DQ, cqh, (h16*)0, DQ, 0, Wuq, NQCR, 0,
        qcr, (h16*)0, (h16*)0, NQCR, 0, 1.f);

    rope_q_kernel<<<(S_LEN * NH) / 8, 256>>>(qcr);
    // Q single fp16
    long long nq = (long long)S_LEN * NQCR;
    quant16_kernel<<<split_grid(nq), blk>>>(qcr, qh, nq);

    // ---- G3: ckv_kr = X @ W_dkv (2-pass A) ----
    bgemm2<<<dim3((DCKV + 127) / 128, S_LEN / 128, 1), blk, SB>>>(
        S_LEN, DCKV, HIDDEN, Xh, Xl, HIDDEN, 0, Wdkv, DCKV, 0,
        ckv, (h16*)0, (h16*)0, DCKV, 0, 1.f);

    rmsnorm_split_kernel<<<S_LEN, 256>>>(ckv, gkv, DKV, DCKV, DKV, ckvnh, ckvnl);
    rope_k_kernel<<<S_LEN / 8, 256>>>(ckv, krh);

    // ---- G4: kv = rmsnorm(c_kv) @ W_ukv (2-pass A, single fp16 out) ----
    bgemm2<<<dim3(NKV / 128, S_LEN / 128, 1), blk, SB>>>(
        S_LEN, NKV, DKV, ckvnh, ckvnl, DKV, 0, Wukv, NKV, 0,
        (float*)0, kvh, (h16*)0, NKV, 0, 1.f);

    build_kT_kernel<<<4096, 256>>>(kvh, krh, kTh);

    // ---- G5: scores[h] = Q[h] @ K[h]^T * scale (single-pass A) ----
    float scale = 1.0f / sqrtf((float)DQR);
    bgemm2<<<dim3(S_LEN / 128, S_LEN / 128, NH), blk, SB>>>(
        S_LEN, S_LEN, DQR,
        qh, (h16*)0, NQCR, (long long)DQR,
        kTh, S_LEN, (long long)DQR * S_LEN,
        sc, (h16*)0, (h16*)0, S_LEN, (long long)S_LEN * S_LEN, scale);

    softmax_fused_kernel<<<NH * S_LEN, 256>>>(sc, Ph);

    // ---- G6: O[h] = P[h] @ V[h] (single-pass A, single fp16 out) ----
    bgemm2<<<dim3(1, S_LEN / 128, NH), blk, SB>>>(
        S_LEN, DH, S_LEN,
        Ph, (h16*)0, S_LEN, (long long)S_LEN * S_LEN,
        kvh + DH, NKV, (long long)2 * DH,
        (float*)0, oh, (h16*)0, NODIM, (long long)DH, 1.f);

    // ---- G7: out = O @ W_o (single-pass A) ----
    bgemm2<<<dim3(HIDDEN / 128, S_LEN / 128, 1), blk, SB>>>(
        S_LEN, HIDDEN, NODIM, oh, (h16*)0, NODIM, 0, Wo, HIDDEN, 0,
        out, (h16*)0, (h16*)0, HIDDEN, 0, 1.f);
}

// round 16
// speedup vs baseline: 3.4313x; 1.1861x over previous
#include <cuda_runtime.h>
#include <cuda_fp16.h>
#include <math.h>
#include <stdint.h>
#include <cstdint>

// ---------------------------------------------------------------------------
// MLA forward — fully single-pass fp16 GEMMs (fp32 accum) via mma.sync
// m16n8k16.f16 + cp.async 3-stage pipeline + ldmatrix.
// Error model (calibrated R13-R15): each fp16 quantization ~1.9e-4 in
// quadrature; full single-pass ≈ 7.3e-4 predicted vs 1e-3 gate.
// Shapes: B=1, S=2048, HIDDEN=7168, NH=32, DQ=1536, DKV=512, DH=128, DR=64
// ---------------------------------------------------------------------------

#define S_LEN   2048
#define HIDDEN  7168
#define NH      32
#define DQ      1536
#define DKV     512
#define DH      128
#define DR      64
#define DQR     (DH + DR)            // 192
#define NQCR    (NH * DQR)           // 6144
#define NKV     (NH * 2 * DH)        // 8192
#define DCKV    (DKV + DR)           // 576
#define NODIM   (NH * DH)            // 4096

typedef __half h16;

// ---------------- scratch (device globals; no allocation allowed) ----------
__device__ float g_cq [(long long)S_LEN * DQ];
__device__ float g_qcr[(long long)S_LEN * NQCR];
__device__ float g_ckv[(long long)S_LEN * DCKV];
__device__ float g_sc [(long long)NH * S_LEN * S_LEN];

__device__ h16 g_Xh [(long long)S_LEN * HIDDEN];
__device__ h16 g_Wdq [(long long)HIDDEN * DQ];
__device__ h16 g_Wuq [(long long)DQ * NQCR];
__device__ h16 g_Wdkv[(long long)HIDDEN * DCKV];
__device__ h16 g_Wukv[(long long)DKV * NKV];
__device__ h16 g_Wo  [(long long)NODIM * HIDDEN];
__device__ h16 g_cqh [(long long)S_LEN * DQ];
__device__ h16 g_qh  [(long long)S_LEN * NQCR];
__device__ h16 g_ckvnh[(long long)S_LEN * DKV];
__device__ h16 g_krh [(long long)S_LEN * DR];
__device__ h16 g_kvh [(long long)S_LEN * NKV];
__device__ h16 g_kTh [(long long)NH * DQR * S_LEN];
__device__ h16 g_Ph  [(long long)NH * S_LEN * S_LEN];
__device__ h16 g_oh  [(long long)S_LEN * NODIM];

// ---------------------------------------------------------------------------
// fp32 -> fp16 quantize. n % 4 == 0.
__global__ void quant16_kernel(const float* __restrict__ s,
                               h16* __restrict__ h, long long n)
{
    for (long long i = ((long long)blockIdx.x * blockDim.x + threadIdx.x) * 4;
         i < n; i += (long long)gridDim.x * blockDim.x * 4) {
        float4 v = *(const float4*)(s + i);
        *(half2*)(h + i)     = __halves2half2(__float2half_rn(v.x), __float2half_rn(v.y));
        *(half2*)(h + i + 2) = __halves2half2(__float2half_rn(v.z), __float2half_rn(v.w));
    }
}

// ---------------------------------------------------------------------------
#define MMA_OP(ac, a, b)                                                     \
    asm volatile("mma.sync.aligned.m16n8k16.row.col.f32.f16.f16.f32 "        \
        "{%0,%1,%2,%3}, {%4,%5,%6,%7}, {%8,%9}, {%0,%1,%2,%3};"              \
        : "+f"((ac)[0]), "+f"((ac)[1]), "+f"((ac)[2]), "+f"((ac)[3])         \
        : "r"((a)[0]), "r"((a)[1]), "r"((a)[2]), "r"((a)[3]),                \
          "r"((b)[0]), "r"((b)[1]))

#define CP16(dst, src) \
    asm volatile("cp.async.cg.shared.global [%0], [%1], 16;" :: "r"(dst), "l"(src))
#define CP_COMMIT() asm volatile("cp.async.commit_group;")
#define CP_WAIT1()  asm volatile("cp.async.wait_group 1;")

#define LDSM_X4(f, addr)                                                      \
    asm volatile("ldmatrix.sync.aligned.m8n8.x4.shared.b16 {%0,%1,%2,%3}, [%4];" \
        : "=r"((f)[0]), "=r"((f)[1]), "=r"((f)[2]), "=r"((f)[3]) : "r"(addr))
#define LDSM_X4T(r0, r1, r2, r3, addr)                                        \
    asm volatile("ldmatrix.sync.aligned.m8n8.x4.trans.shared.b16 {%0,%1,%2,%3}, [%4];" \
        : "=r"(r0), "=r"(r1), "=r"(r2), "=r"(r3) : "r"(addr))

// ---------------------------------------------------------------------------
// GEMM, single-pass fp16, fp32 accum: C = alpha * A·B.
// 128x128 tile, BK=32, 3-stage cp.async, 256 threads, 8 warps of 32x64.
// A [M][K] k-contig. B [K][N] n-contig.
// Outputs: fp32 C and/or fp16 Ch.
// M%128==0, K%32==0, N%8==0 effective (clamped loads), lda/ldb%8==0.
// Stage = 19 KB -> 57 KB total: 2 CTAs/SM for cross-CTA latency hiding.
// ---------------------------------------------------------------------------
#define A_ST  (128 * 40)
#define B_ST  (32 * 136)
#define STG   (A_ST + B_ST)                   // 9472 elems
#define SMEM_BYTES (3 * STG * 2)              // 56832 bytes

__global__ __launch_bounds__(256)
void bgemm1(int M, int N, int K,
            const h16* __restrict__ A, int lda, long long sA,
            const h16* __restrict__ B, int ldb, long long sB,
            float* __restrict__ C, h16* __restrict__ Ch,
            int ldc, long long sC, float alpha)
{
    extern __shared__ __align__(16) char dynsmem[];
    uint32_t sbase = (uint32_t)__cvta_generic_to_shared(dynsmem);

    const h16* pA = A + (long long)blockIdx.z * sA;
    const h16* pB = B + (long long)blockIdx.z * sB;

    const int tid = threadIdx.x;
    const int bm = blockIdx.y << 7;
    const int bn = blockIdx.x << 7;

    const int lane = tid & 31;
    const int warp = tid >> 5;
    const int wm = (warp & 3) << 5;
    const int wn = (warp >> 2) << 6;
    const int g  = lane >> 2;
    const int qt = (lane & 3) << 1;

    const int nk = K >> 5;

    float acc[2][8][4];
#pragma unroll
    for (int i = 0; i < 2; i++)
#pragma unroll
        for (int j = 0; j < 8; j++)
#pragma unroll
            for (int c = 0; c < 4; c++) acc[i][j][c] = 0.f;

    auto issue_stage = [&](int stg, int k0) {
        uint32_t sb = sbase + (uint32_t)(stg * STG * 2);
#pragma unroll
        for (int r = 0; r < 2; r++) {
            const int c = tid + (r << 8);
            // A: row = c/4, k-chunk = (c%4)*8
            const int arow = c >> 2;
            const int ak   = (c & 3) << 3;
            const long long aoff = (long long)(bm + arow) * lda + k0 + ak;
            const uint32_t dA = sb + (uint32_t)((arow * 40 + ak) * 2);
            CP16(dA, pA + aoff);
            // B: k-row = c/16, n-chunk = (c%16)*8
            const int krow = c >> 4;
            const int nc   = (c & 15) << 3;
            int gn = bn + nc;
            if (gn > N - 8) gn = N - 8;
            const long long boff = (long long)(k0 + krow) * ldb + gn;
            const uint32_t dB = sb + (uint32_t)((A_ST + krow * 136 + nc) * 2);
            CP16(dB, pB + boff);
        }
    };

    issue_stage(0, 0);
    CP_COMMIT();
    if (nk > 1) issue_stage(1, 32);
    CP_COMMIT();

    const int ar  = lane & 15;
    const int hi8 = (lane & 16) >> 1;

    for (int kt = 0; kt < nk; kt++) {
        CP_WAIT1();
        __syncthreads();

        if (kt + 2 < nk) issue_stage((kt + 2) % 3, (kt + 2) << 5);
        CP_COMMIT();

        const uint32_t sb = sbase + (uint32_t)((kt % 3) * STG * 2);
        const uint32_t aA = sb;
        const uint32_t bB = sb + A_ST * 2;

#pragma unroll
        for (int ks = 0; ks < 2; ks++) {
            const int ka = (ks << 4) + hi8;
            const uint32_t adr0 = aA + (uint32_t)(((wm + ar) * 40 + ka) * 2);
            uint32_t af0[4], af1[4];
            LDSM_X4(af0, adr0);
            LDSM_X4(af1, adr0 + 16 * 80);

            const int kb = (ks << 4) + ar;
            const uint32_t bdr = bB + (uint32_t)((kb * 136 + wn + hi8) * 2);
            uint32_t bf[8][2];
#pragma unroll
            for (int jp = 0; jp < 4; jp++)
                LDSM_X4T(bf[2*jp][0], bf[2*jp][1], bf[2*jp+1][0], bf[2*jp+1][1],
                         bdr + jp * 32);

#pragma unroll
            for (int jn = 0; jn < 8; jn++) {
                MMA_OP(acc[0][jn], af0, bf[jn]);
                MMA_OP(acc[1][jn], af1, bf[jn]);
            }
        }
    }

    float* pC = C ? C + (long long)blockIdx.z * sC : (float*)0;
    h16* pCh = Ch ? Ch + (long long)blockIdx.z * sC : (h16*)0;

#pragma unroll
    for (int im = 0; im < 2; im++) {
#pragma unroll
        for (int jn = 0; jn < 8; jn++) {
            const int row = bm + wm + (im << 4) + g;
            const int col = bn + wn + (jn << 3) + qt;
            if (col < N) {
                const float v0 = alpha * acc[im][jn][0];
                const float v1 = alpha * acc[im][jn][1];
                const float v2 = alpha * acc[im][jn][2];
                const float v3 = alpha * acc[im][jn][3];
                if (pC) {
                    *(float2*)(pC + (long long)row * ldc + col) = make_float2(v0, v1);
                    *(float2*)(pC + (long long)(row + 8) * ldc + col) = make_float2(v2, v3);
                }
                if (pCh) {
                    *(half2*)(pCh + (long long)row * ldc + col) =
                        __halves2half2(__float2half_rn(v0), __float2half_rn(v1));
                    *(half2*)(pCh + (long long)(row + 8) * ldc + col) =
                        __halves2half2(__float2half_rn(v2), __float2half_rn(v3));
                }
            }
        }
    }
}

// ---------------------------------------------------------------------------
// RMSNorm over first W cols (row stride ld in, ldo out), single fp16 out.
// ---------------------------------------------------------------------------
__global__ void rmsnorm_quant_kernel(const float* __restrict__ x,
                                     const float* __restrict__ g,
                                     int W, int ld, int ldo,
                                     h16* __restrict__ oh)
{
    __shared__ float red[32];
    const float* row = x + (long long)blockIdx.x * ld;
    float s = 0.f;
    for (int i = threadIdx.x; i < W; i += blockDim.x) {
        float v = row[i];
        s += v * v;
    }
#pragma unroll
    for (int o = 16; o; o >>= 1) s += __shfl_xor_sync(0xffffffffu, s, o);
    int w = threadIdx.x >> 5, l = threadIdx.x & 31;
    if (l == 0) red[w] = s;
    __syncthreads();
    if (w == 0) {
        float t = (l < (blockDim.x >> 5)) ? red[l] : 0.f;
#pragma unroll
        for (int o = 16; o; o >>= 1) t += __shfl_xor_sync(0xffffffffu, t, o);
        if (l == 0) red[0] = t;
    }
    __syncthreads();
    float scale = rsqrtf(red[0] / (float)W + 1.1920929e-07f);
    h16* ohr = oh + (long long)blockIdx.x * ldo;
    for (int i = threadIdx.x; i < W; i += blockDim.x)
        ohr[i] = __float2half_rn(row[i] * scale * g[i]);
}

// ---------------------------------------------------------------------------
// RoPE (D=64)
// ---------------------------------------------------------------------------
__device__ __forceinline__ void rope_pair(float* base, int j, int t)
{
    float ex  = (2.0f * (float)j) / 64.0f;
    float inv = 1.0f / powf(10000.0f, ex);
    float fr  = (float)t * inv;
    float c   = cosf(fr);
    float sn  = sinf(fr);
    float x1 = base[j];
    float x2 = base[j + 32];
    base[j]      = x1 * c - x2 * sn;
    base[j + 32] = x2 * c + x1 * sn;
}

__global__ void rope_q_kernel(float* __restrict__ qcr)
{
    int item = blockIdx.x * (blockDim.x >> 5) + (threadIdx.x >> 5);
    if (item >= S_LEN * NH) return;
    int s = item >> 5;
    int h = item & 31;
    int j = threadIdx.x & 31;
    rope_pair(qcr + (long long)s * NQCR + h * DQR + DH, j, s);
}

// rope on ckv cols 512..575, write single fp16 k_r
__global__ void rope_k_kernel(float* __restrict__ ckv, h16* __restrict__ krh)
{
    int item = blockIdx.x * (blockDim.x >> 5) + (threadIdx.x >> 5);
    if (item >= S_LEN) return;
    int j = threadIdx.x & 31;
    float* base = ckv + (long long)item * DCKV + DKV;
    rope_pair(base, j, item);
    krh[(long long)item * DR + j]      = __float2half_rn(base[j]);
    krh[(long long)item * DR + j + 32] = __float2half_rn(base[j + 32]);
}

// ---------------------------------------------------------------------------
// kT[h][d][s] single fp16 from kv fp16 + roped k_r fp16.
// ---------------------------------------------------------------------------
__global__ void build_kT_kernel(const h16* __restrict__ kvh,
                                const h16* __restrict__ krh,
                                h16* __restrict__ kTh)
{
    const long long total = (long long)NH * DQR * S_LEN;
    for (long long i = (long long)blockIdx.x * blockDim.x + threadIdx.x;
         i < total; i += (long long)gridDim.x * blockDim.x) {
        int s = (int)(i % S_LEN);
        long long t = i / S_LEN;
        int d = (int)(t % DQR);
        int h = (int)(t / DQR);
        kTh[i] = (d < DH) ? kvh[(long long)s * NKV + h * 2 * DH + d]
                          : krh[(long long)s * DR + (d - DH)];
    }
}

// ---------------------------------------------------------------------------
// Single-pass smem softmax (width 2048), single fp16 P output.
// ---------------------------------------------------------------------------
__global__ __launch_bounds__(256)
void softmax_fused_kernel(const float* __restrict__ sc, h16* __restrict__ ph)
{
    __shared__ float srow[S_LEN];
    __shared__ float red[32];
    const float* row = sc + (long long)blockIdx.x * S_LEN;
    h16* hrow = ph + (long long)blockIdx.x * S_LEN;
    const int w = threadIdx.x >> 5, l = threadIdx.x & 31;

    float m = -3.402823466e+38f;
#pragma unroll
    for (int r = 0; r < 2; r++) {
        const int i = (threadIdx.x + (r << 8)) << 2;
        float4 v = *(const float4*)(row + i);
        *(float4*)(srow + i) = v;
        m = fmaxf(m, fmaxf(fmaxf(v.x, v.y), fmaxf(v.z, v.w)));
    }
#pragma unroll
    for (int o = 16; o; o >>= 1) m = fmaxf(m, __shfl_xor_sync(0xffffffffu, m, o));
    if (l == 0) red[w] = m;
    __syncthreads();
    if (w == 0) {
        float t = (l < 8) ? red[l] : -3.402823466e+38f;
#pragma unroll
        for (int o = 16; o; o >>= 1) t = fmaxf(t, __shfl_xor_sync(0xffffffffu, t, o));
        if (l == 0) red[0] = t;
    }
    __syncthreads();
    const float M = red[0];

    float s = 0.f;
#pragma unroll
    for (int r = 0; r < 2; r++) {
        const int i = (threadIdx.x + (r << 8)) << 2;
        float4 v = *(float4*)(srow + i);
        v.x = __expf(v.x - M);
        v.y = __expf(v.y - M);
        v.z = __expf(v.z - M);
        v.w = __expf(v.w - M);
        *(float4*)(srow + i) = v;
        s += (v.x + v.y) + (v.z + v.w);
    }
#pragma unroll
    for (int o = 16; o; o >>= 1) s += __shfl_xor_sync(0xffffffffu, s, o);
    if (l == 0) red[w] = s;
    __syncthreads();
    if (w == 0) {
        float t = (l < 8) ? red[l] : 0.f;
#pragma unroll
        for (int o = 16; o; o >>= 1) t += __shfl_xor_sync(0xffffffffu, t, o);
        if (l == 0) red[0] = t;
    }
    __syncthreads();
    const float inv = 1.0f / red[0];

#pragma unroll
    for (int r = 0; r < 2; r++) {
        const int i = (threadIdx.x + (r << 8)) << 2;
        float4 v = *(float4*)(srow + i);
        *(half2*)(hrow + i) =
            __halves2half2(__float2half_rn(v.x * inv), __float2half_rn(v.y * inv));
        *(half2*)(hrow + i + 2) =
            __halves2half2(__float2half_rn(v.z * inv), __float2half_rn(v.w * inv));
    }
}

// ---------------------------------------------------------------------------
static inline int split_grid(long long n)
{
    long long b = (n / 4 + 255) / 256;
    if (b > 8192) b = 8192;
    return (int)b;
}

extern "C" void kernel_launch(void* const* d_in, const int* in_sizes, int n_in,
                              void* d_out, int out_size)
{
    const float* X     = (const float*)d_in[0];
    const float* W_dq  = (const float*)d_in[1];
    const float* gq    = (const float*)d_in[2];
    const float* W_uq  = (const float*)d_in[3];
    const float* W_dkv = (const float*)d_in[4];
    const float* gkv   = (const float*)d_in[5];
    const float* W_ukv = (const float*)d_in[6];
    const float* W_o   = (const float*)d_in[7];
    float* out = (float*)d_out;

    float *cq, *qcr, *ckv, *sc;
    h16 *Xh,*Wdq,*Wuq,*Wdkv,*Wukv,*Wo;
    h16 *cqh,*qh,*ckvnh,*krh,*kvh,*kTh,*Ph,*oh;

    cudaGetSymbolAddress((void**)&cq,  g_cq);
    cudaGetSymbolAddress((void**)&qcr, g_qcr);
    cudaGetSymbolAddress((void**)&ckv, g_ckv);
    cudaGetSymbolAddress((void**)&sc,  g_sc);
    cudaGetSymbolAddress((void**)&Xh,  g_Xh);
    cudaGetSymbolAddress((void**)&Wdq,  g_Wdq);
    cudaGetSymbolAddress((void**)&Wuq,  g_Wuq);
    cudaGetSymbolAddress((void**)&Wdkv, g_Wdkv);
    cudaGetSymbolAddress((void**)&Wukv, g_Wukv);
    cudaGetSymbolAddress((void**)&Wo,   g_Wo);
    cudaGetSymbolAddress((void**)&cqh, g_cqh);
    cudaGetSymbolAddress((void**)&qh,  g_qh);
    cudaGetSymbolAddress((void**)&ckvnh, g_ckvnh);
    cudaGetSymbolAddress((void**)&krh, g_krh);
    cudaGetSymbolAddress((void**)&kvh, g_kvh);
    cudaGetSymbolAddress((void**)&kTh, g_kTh);
    cudaGetSymbolAddress((void**)&Ph,  g_Ph);
    cudaGetSymbolAddress((void**)&oh,  g_oh);

    cudaFuncSetAttribute(bgemm1, cudaFuncAttributeMaxDynamicSharedMemorySize, SMEM_BYTES);

    dim3 blk(256);
    const int SB = SMEM_BYTES;

    // ---- quantize inputs to fp16 ----
    long long nX = (long long)S_LEN * HIDDEN;
    quant16_kernel<<<split_grid(nX), blk>>>(X, Xh, nX);
    quant16_kernel<<<split_grid((long long)HIDDEN * DQ), blk>>>(W_dq, Wdq, (long long)HIDDEN * DQ);
    quant16_kernel<<<split_grid((long long)DQ * NQCR), blk>>>(W_uq, Wuq, (long long)DQ * NQCR);
    quant16_kernel<<<split_grid((long long)HIDDEN * DCKV), blk>>>(W_dkv, Wdkv, (long long)HIDDEN * DCKV);
    quant16_kernel<<<split_grid((long long)DKV * NKV), blk>>>(W_ukv, Wukv, (long long)DKV * NKV);
    quant16_kernel<<<split_grid((long long)NODIM * HIDDEN), blk>>>(W_o, Wo, (long long)NODIM * HIDDEN);

    // ---- G1: c_q = X @ W_dq ----
    bgemm1<<<dim3(DQ / 128, S_LEN / 128, 1), blk, SB>>>(
        S_LEN, DQ, HIDDEN, Xh, HIDDEN, 0, Wdq, DQ, 0,
        cq, (h16*)0, DQ, 0, 1.f);

    rmsnorm_quant_kernel<<<S_LEN, 256>>>(cq, gq, DQ, DQ, DQ, cqh);

    // ---- G2: qcr = c_qn @ W_uq ----
    bgemm1<<<dim3(NQCR / 128, S_LEN / 128, 1), blk, SB>>>(
        S_LEN, NQCR, DQ, cqh, DQ, 0, Wuq, NQCR, 0,
        qcr, (h16*)0, NQCR, 0, 1.f);

    rope_q_kernel<<<(S_LEN * NH) / 8, 256>>>(qcr);
    long long nq = (long long)S_LEN * NQCR;
    quant16_kernel<<<split_grid(nq), blk>>>(qcr, qh, nq);

    // ---- G3: ckv_kr = X @ W_dkv ----
    bgemm1<<<dim3((DCKV + 127) / 128, S_LEN / 128, 1), blk, SB>>>(
        S_LEN, DCKV, HIDDEN, Xh, HIDDEN, 0, Wdkv, DCKV, 0,
        ckv, (h16*)0, DCKV, 0, 1.f);

    rmsnorm_quant_kernel<<<S_LEN, 256>>>(ckv, gkv, DKV, DCKV, DKV, ckvnh);
    rope_k_kernel<<<S_LEN / 8, 256>>>(ckv, krh);

    // ---- G4: kv = c_kvn @ W_ukv (single fp16 out) ----
    bgemm1<<<dim3(NKV / 128, S_LEN / 128, 1), blk, SB>>>(
        S_LEN, NKV, DKV, ckvnh, DKV, 0, Wukv, NKV, 0,
        (float*)0, kvh, NKV, 0, 1.f);

    build_kT_kernel<<<4096, 256>>>(kvh, krh, kTh);

    // ---- G5: scores[h] = Q[h] @ K[h]^T * scale ----
    float scale = 1.0f / sqrtf((float)DQR);
    bgemm1<<<dim3(S_LEN / 128, S_LEN / 128, NH), blk, SB>>>(
        S_LEN, S_LEN, DQR,
        qh, NQCR, (long long)DQR,
        kTh, S_LEN, (long long)DQR * S_LEN,
        sc, (h16*)0, S_LEN, (long long)S_LEN * S_LEN, scale);

    softmax_fused_kernel<<<NH * S_LEN, 256>>>(sc, Ph);

    // ---- G6: O[h] = P[h] @ V[h] (single fp16 out) ----
    bgemm1<<<dim3(1, S_LEN / 128, NH), blk, SB>>>(
        S_LEN, DH, S_LEN,
        Ph, S_LEN, (long long)S_LEN * S_LEN,
        kvh + DH, NKV, (long long)2 * DH,
        (float*)0, oh, NODIM, (long long)DH, 1.f);

    // ---- G7: out = O @ W_o ----
    bgemm1<<<dim3(HIDDEN / 128, S_LEN / 128, 1), blk, SB>>>(
        S_LEN, HIDDEN, NODIM, oh, NODIM, 0, Wo, HIDDEN, 0,
        out, (h16*)0, HIDDEN, 0, 1.f);
}

// round 17
// speedup vs baseline: 3.7974x; 1.1067x over previous
#include <cuda_runtime.h>
#include <cuda_fp16.h>
#include <math.h>
#include <stdint.h>
#include <cstdint>

// ---------------------------------------------------------------------------
// MLA forward — fully single-pass fp16 GEMMs (fp32 accum) via mma.sync
// m16n8k16.f16 + cp.async 3-stage pipeline + ldmatrix.
// R17: fp16 scores, G1+G3 merged (concat weights), fp16 Q + in-place rope.
// Shapes: B=1, S=2048, HIDDEN=7168, NH=32, DQ=1536, DKV=512, DH=128, DR=64
// ---------------------------------------------------------------------------

#define S_LEN   2048
#define HIDDEN  7168
#define NH      32
#define DQ      1536
#define DKV     512
#define DH      128
#define DR      64
#define DQR     (DH + DR)            // 192
#define NQCR    (NH * DQR)           // 6144
#define NKV     (NH * 2 * DH)        // 8192
#define DCKV    (DKV + DR)           // 576
#define NC      (DQ + DCKV)          // 2112 (combined G1+G3 output width)
#define NODIM   (NH * DH)            // 4096

typedef __half h16;

// ---------------- scratch (device globals; no allocation allowed) ----------
__device__ float g_c  [(long long)S_LEN * NC];          // combined c_q | c_kv | k_r

__device__ h16 g_Xh  [(long long)S_LEN * HIDDEN];
__device__ h16 g_Wc  [(long long)HIDDEN * NC];          // W_dq | W_dkv concatenated
__device__ h16 g_Wuq [(long long)DQ * NQCR];
__device__ h16 g_Wukv[(long long)DKV * NKV];
__device__ h16 g_Wo  [(long long)NODIM * HIDDEN];
__device__ h16 g_cqh [(long long)S_LEN * DQ];
__device__ h16 g_qh  [(long long)S_LEN * NQCR];
__device__ h16 g_ckvnh[(long long)S_LEN * DKV];
__device__ h16 g_krh [(long long)S_LEN * DR];
__device__ h16 g_kvh [(long long)S_LEN * NKV];
__device__ h16 g_kTh [(long long)NH * DQR * S_LEN];
__device__ h16 g_sch [(long long)NH * S_LEN * S_LEN];   // fp16 scores
__device__ h16 g_Ph  [(long long)NH * S_LEN * S_LEN];
__device__ h16 g_oh  [(long long)S_LEN * NODIM];

// ---------------------------------------------------------------------------
// fp32 -> fp16 quantize, flat. n % 4 == 0.
__global__ void quant16_kernel(const float* __restrict__ s,
                               h16* __restrict__ h, long long n)
{
    for (long long i = ((long long)blockIdx.x * blockDim.x + threadIdx.x) * 4;
         i < n; i += (long long)gridDim.x * blockDim.x * 4) {
        float4 v = *(const float4*)(s + i);
        *(half2*)(h + i)     = __halves2half2(__float2half_rn(v.x), __float2half_rn(v.y));
        *(half2*)(h + i + 2) = __halves2half2(__float2half_rn(v.z), __float2half_rn(v.w));
    }
}

// fp32 W[K][N] -> fp16 dst[K][ldc] at column offset co. N % 4 == 0, co % 4 == 0.
__global__ void quant16_pad_kernel(const float* __restrict__ s,
                                   h16* __restrict__ dst,
                                   long long total, int N, int ldc, int co)
{
    for (long long i = ((long long)blockIdx.x * blockDim.x + threadIdx.x) * 4;
         i < total; i += (long long)gridDim.x * blockDim.x * 4) {
        float4 v = *(const float4*)(s + i);
        const long long row = i / N;
        const int col = (int)(i - row * N);
        h16* d = dst + row * ldc + co + col;
        *(half2*)(d)     = __halves2half2(__float2half_rn(v.x), __float2half_rn(v.y));
        *(half2*)(d + 2) = __halves2half2(__float2half_rn(v.z), __float2half_rn(v.w));
    }
}

// ---------------------------------------------------------------------------
#define MMA_OP(ac, a, b)                                                     \
    asm volatile("mma.sync.aligned.m16n8k16.row.col.f32.f16.f16.f32 "        \
        "{%0,%1,%2,%3}, {%4,%5,%6,%7}, {%8,%9}, {%0,%1,%2,%3};"              \
        : "+f"((ac)[0]), "+f"((ac)[1]), "+f"((ac)[2]), "+f"((ac)[3])         \
        : "r"((a)[0]), "r"((a)[1]), "r"((a)[2]), "r"((a)[3]),                \
          "r"((b)[0]), "r"((b)[1]))

#define CP16(dst, src) \
    asm volatile("cp.async.cg.shared.global [%0], [%1], 16;" :: "r"(dst), "l"(src))
#define CP_COMMIT() asm volatile("cp.async.commit_group;")
#define CP_WAIT1()  asm volatile("cp.async.wait_group 1;")

#define LDSM_X4(f, addr)                                                      \
    asm volatile("ldmatrix.sync.aligned.m8n8.x4.shared.b16 {%0,%1,%2,%3}, [%4];" \
        : "=r"((f)[0]), "=r"((f)[1]), "=r"((f)[2]), "=r"((f)[3]) : "r"(addr))
#define LDSM_X4T(r0, r1, r2, r3, addr)                                        \
    asm volatile("ldmatrix.sync.aligned.m8n8.x4.trans.shared.b16 {%0,%1,%2,%3}, [%4];" \
        : "=r"(r0), "=r"(r1), "=r"(r2), "=r"(r3) : "r"(addr))

// ---------------------------------------------------------------------------
// GEMM, single-pass fp16, fp32 accum: C = alpha * A·B.
// 128x128 tile, BK=32, 3-stage cp.async, 256 threads, 8 warps of 32x64.
// A [M][K] k-contig. B [K][N] n-contig. Outputs fp32 C and/or fp16 Ch.
// M%128==0, K%32==0, N%8==0 (clamped loads / masked stores), lda/ldb%8==0.
// ---------------------------------------------------------------------------
#define A_ST  (128 * 40)
#define B_ST  (32 * 136)
#define STG   (A_ST + B_ST)
#define SMEM_BYTES (3 * STG * 2)              // 56832 bytes -> 2 CTAs/SM

__global__ __launch_bounds__(256)
void bgemm1(int M, int N, int K,
            const h16* __restrict__ A, int lda, long long sA,
            const h16* __restrict__ B, int ldb, long long sB,
            float* __restrict__ C, h16* __restrict__ Ch,
            int ldc, long long sC, float alpha)
{
    extern __shared__ __align__(16) char dynsmem[];
    uint32_t sbase = (uint32_t)__cvta_generic_to_shared(dynsmem);

    const h16* pA = A + (long long)blockIdx.z * sA;
    const h16* pB = B + (long long)blockIdx.z * sB;

    const int tid = threadIdx.x;
    const int bm = blockIdx.y << 7;
    const int bn = blockIdx.x << 7;

    const int lane = tid & 31;
    const int warp = tid >> 5;
    const int wm = (warp & 3) << 5;
    const int wn = (warp >> 2) << 6;
    const int g  = lane >> 2;
    const int qt = (lane & 3) << 1;

    const int nk = K >> 5;

    float acc[2][8][4];
#pragma unroll
    for (int i = 0; i < 2; i++)
#pragma unroll
        for (int j = 0; j < 8; j++)
#pragma unroll
            for (int c = 0; c < 4; c++) acc[i][j][c] = 0.f;

    auto issue_stage = [&](int stg, int k0) {
        uint32_t sb = sbase + (uint32_t)(stg * STG * 2);
#pragma unroll
        for (int r = 0; r < 2; r++) {
            const int c = tid + (r << 8);
            const int arow = c >> 2;
            const int ak   = (c & 3) << 3;
            const long long aoff = (long long)(bm + arow) * lda + k0 + ak;
            const uint32_t dA = sb + (uint32_t)((arow * 40 + ak) * 2);
            CP16(dA, pA + aoff);
            const int krow = c >> 4;
            const int nc   = (c & 15) << 3;
            int gn = bn + nc;
            if (gn > N - 8) gn = N - 8;
            const long long boff = (long long)(k0 + krow) * ldb + gn;
            const uint32_t dB = sb + (uint32_t)((A_ST + krow * 136 + nc) * 2);
            CP16(dB, pB + boff);
        }
    };

    issue_stage(0, 0);
    CP_COMMIT();
    if (nk > 1) issue_stage(1, 32);
    CP_COMMIT();

    const int ar  = lane & 15;
    const int hi8 = (lane & 16) >> 1;

    for (int kt = 0; kt < nk; kt++) {
        CP_WAIT1();
        __syncthreads();

        if (kt + 2 < nk) issue_stage((kt + 2) % 3, (kt + 2) << 5);
        CP_COMMIT();

        const uint32_t sb = sbase + (uint32_t)((kt % 3) * STG * 2);
        const uint32_t aA = sb;
        const uint32_t bB = sb + A_ST * 2;

#pragma unroll
        for (int ks = 0; ks < 2; ks++) {
            const int ka = (ks << 4) + hi8;
            const uint32_t adr0 = aA + (uint32_t)(((wm + ar) * 40 + ka) * 2);
            uint32_t af0[4], af1[4];
            LDSM_X4(af0, adr0);
            LDSM_X4(af1, adr0 + 16 * 80);

            const int kb = (ks << 4) + ar;
            const uint32_t bdr = bB + (uint32_t)((kb * 136 + wn + hi8) * 2);
            uint32_t bf[8][2];
#pragma unroll
            for (int jp = 0; jp < 4; jp++)
                LDSM_X4T(bf[2*jp][0], bf[2*jp][1], bf[2*jp+1][0], bf[2*jp+1][1],
                         bdr + jp * 32);

#pragma unroll
            for (int jn = 0; jn < 8; jn++) {
                MMA_OP(acc[0][jn], af0, bf[jn]);
                MMA_OP(acc[1][jn], af1, bf[jn]);
            }
        }
    }

    float* pC = C ? C + (long long)blockIdx.z * sC : (float*)0;
    h16* pCh = Ch ? Ch + (long long)blockIdx.z * sC : (h16*)0;

#pragma unroll
    for (int im = 0; im < 2; im++) {
#pragma unroll
        for (int jn = 0; jn < 8; jn++) {
            const int row = bm + wm + (im << 4) + g;
            const int col = bn + wn + (jn << 3) + qt;
            if (col < N) {
                const float v0 = alpha * acc[im][jn][0];
                const float v1 = alpha * acc[im][jn][1];
                const float v2 = alpha * acc[im][jn][2];
                const float v3 = alpha * acc[im][jn][3];
                if (pC) {
                    *(float2*)(pC + (long long)row * ldc + col) = make_float2(v0, v1);
                    *(float2*)(pC + (long long)(row + 8) * ldc + col) = make_float2(v2, v3);
                }
                if (pCh) {
                    *(half2*)(pCh + (long long)row * ldc + col) =
                        __halves2half2(__float2half_rn(v0), __float2half_rn(v1));
                    *(half2*)(pCh + (long long)(row + 8) * ldc + col) =
                        __halves2half2(__float2half_rn(v2), __float2half_rn(v3));
                }
            }
        }
    }
}

// ---------------------------------------------------------------------------
// RMSNorm over W cols (input row stride ld, output stride ldo), fp16 out.
// ---------------------------------------------------------------------------
__global__ void rmsnorm_quant_kernel(const float* __restrict__ x,
                                     const float* __restrict__ g,
                                     int W, int ld, int ldo,
                                     h16* __restrict__ oh)
{
    __shared__ float red[32];
    const float* row = x + (long long)blockIdx.x * ld;
    float s = 0.f;
    for (int i = threadIdx.x; i < W; i += blockDim.x) {
        float v = row[i];
        s += v * v;
    }
#pragma unroll
    for (int o = 16; o; o >>= 1) s += __shfl_xor_sync(0xffffffffu, s, o);
    int w = threadIdx.x >> 5, l = threadIdx.x & 31;
    if (l == 0) red[w] = s;
    __syncthreads();
    if (w == 0) {
        float t = (l < (blockDim.x >> 5)) ? red[l] : 0.f;
#pragma unroll
        for (int o = 16; o; o >>= 1) t += __shfl_xor_sync(0xffffffffu, t, o);
        if (l == 0) red[0] = t;
    }
    __syncthreads();
    float scale = rsqrtf(red[0] / (float)W + 1.1920929e-07f);
    h16* ohr = oh + (long long)blockIdx.x * ldo;
    for (int i = threadIdx.x; i < W; i += blockDim.x)
        ohr[i] = __float2half_rn(row[i] * scale * g[i]);
}

// ---------------------------------------------------------------------------
// RoPE (D=64)
// ---------------------------------------------------------------------------
__device__ __forceinline__ void rope_coeff(int j, int t, float& c, float& sn)
{
    float ex  = (2.0f * (float)j) / 64.0f;
    float inv = 1.0f / powf(10000.0f, ex);
    float fr  = (float)t * inv;
    c  = cosf(fr);
    sn = sinf(fr);
}

// in-place rope on fp16 q_r slices of qh
__global__ void rope_q16_kernel(h16* __restrict__ qh)
{
    int item = blockIdx.x * (blockDim.x >> 5) + (threadIdx.x >> 5);
    if (item >= S_LEN * NH) return;
    int s = item >> 5;
    int h = item & 31;
    int j = threadIdx.x & 31;
    h16* base = qh + (long long)s * NQCR + h * DQR + DH;
    float c, sn;
    rope_coeff(j, s, c, sn);
    float x1 = __half2float(base[j]);
    float x2 = __half2float(base[j + 32]);
    base[j]      = __float2half_rn(x1 * c - x2 * sn);
    base[j + 32] = __float2half_rn(x2 * c + x1 * sn);
}

// rope on fp32 k_r source (stride ld), write fp16 krh
__global__ void rope_k_kernel(const float* __restrict__ kr, int ld,
                              h16* __restrict__ krh)
{
    int item = blockIdx.x * (blockDim.x >> 5) + (threadIdx.x >> 5);
    if (item >= S_LEN) return;
    int j = threadIdx.x & 31;
    const float* base = kr + (long long)item * ld;
    float c, sn;
    rope_coeff(j, item, c, sn);
    float x1 = base[j];
    float x2 = base[j + 32];
    krh[(long long)item * DR + j]      = __float2half_rn(x1 * c - x2 * sn);
    krh[(long long)item * DR + j + 32] = __float2half_rn(x2 * c + x1 * sn);
}

// ---------------------------------------------------------------------------
// kT[h][d][s] single fp16 from kv fp16 + roped k_r fp16.
// ---------------------------------------------------------------------------
__global__ void build_kT_kernel(const h16* __restrict__ kvh,
                                const h16* __restrict__ krh,
                                h16* __restrict__ kTh)
{
    const long long total = (long long)NH * DQR * S_LEN;
    for (long long i = (long long)blockIdx.x * blockDim.x + threadIdx.x;
         i < total; i += (long long)gridDim.x * blockDim.x) {
        int s = (int)(i % S_LEN);
        long long t = i / S_LEN;
        int d = (int)(t % DQR);
        int h = (int)(t / DQR);
        kTh[i] = (d < DH) ? kvh[(long long)s * NKV + h * 2 * DH + d]
                          : krh[(long long)s * DR + (d - DH)];
    }
}

// ---------------------------------------------------------------------------
// Single-pass smem softmax (width 2048) on fp16 scores, fp16 P out.
// ---------------------------------------------------------------------------
__global__ __launch_bounds__(256)
void softmax_fused_kernel(const h16* __restrict__ sc, h16* __restrict__ ph)
{
    __shared__ float srow[S_LEN];
    __shared__ float red[32];
    const h16* row = sc + (long long)blockIdx.x * S_LEN;
    h16* hrow = ph + (long long)blockIdx.x * S_LEN;
    const int w = threadIdx.x >> 5, l = threadIdx.x & 31;

    float m = -3.402823466e+38f;
#pragma unroll
    for (int r = 0; r < 2; r++) {
        const int i = (threadIdx.x + (r << 8)) << 2;
        half2 a = *(const half2*)(row + i);
        half2 b = *(const half2*)(row + i + 2);
        float4 v = make_float4(__half2float(a.x), __half2float(a.y),
                               __half2float(b.x), __half2float(b.y));
        *(float4*)(srow + i) = v;
        m = fmaxf(m, fmaxf(fmaxf(v.x, v.y), fmaxf(v.z, v.w)));
    }
#pragma unroll
    for (int o = 16; o; o >>= 1) m = fmaxf(m, __shfl_xor_sync(0xffffffffu, m, o));
    if (l == 0) red[w] = m;
    __syncthreads();
    if (w == 0) {
        float t = (l < 8) ? red[l] : -3.402823466e+38f;
#pragma unroll
        for (int o = 16; o; o >>= 1) t = fmaxf(t, __shfl_xor_sync(0xffffffffu, t, o));
        if (l == 0) red[0] = t;
    }
    __syncthreads();
    const float M = red[0];

    float s = 0.f;
#pragma unroll
    for (int r = 0; r < 2; r++) {
        const int i = (threadIdx.x + (r << 8)) << 2;
        float4 v = *(float4*)(srow + i);
        v.x = __expf(v.x - M);
        v.y = __expf(v.y - M);
        v.z = __expf(v.z - M);
        v.w = __expf(v.w - M);
        *(float4*)(srow + i) = v;
        s += (v.x + v.y) + (v.z + v.w);
    }
#pragma unroll
    for (int o = 16; o; o >>= 1) s += __shfl_xor_sync(0xffffffffu, s, o);
    if (l == 0) red[w] = s;
    __syncthreads();
    if (w == 0) {
        float t = (l < 8) ? red[l] : 0.f;
#pragma unroll
        for (int o = 16; o; o >>= 1) t += __shfl_xor_sync(0xffffffffu, t, o);
        if (l == 0) red[0] = t;
    }
    __syncthreads();
    const float inv = 1.0f / red[0];

#pragma unroll
    for (int r = 0; r < 2; r++) {
        const int i = (threadIdx.x + (r << 8)) << 2;
        float4 v = *(float4*)(srow + i);
        *(half2*)(hrow + i) =
            __halves2half2(__float2half_rn(v.x * inv), __float2half_rn(v.y * inv));
        *(half2*)(hrow + i + 2) =
            __halves2half2(__float2half_rn(v.z * inv), __float2half_rn(v.w * inv));
    }
}

// ---------------------------------------------------------------------------
static inline int split_grid(long long n)
{
    long long b = (n / 4 + 255) / 256;
    if (b > 8192) b = 8192;
    return (int)b;
}

extern "C" void kernel_launch(void* const* d_in, const int* in_sizes, int n_in,
                              void* d_out, int out_size)
{
    const float* X     = (const float*)d_in[0];
    const float* W_dq  = (const float*)d_in[1];
    const float* gq    = (const float*)d_in[2];
    const float* W_uq  = (const float*)d_in[3];
    const float* W_dkv = (const float*)d_in[4];
    const float* gkv   = (const float*)d_in[5];
    const float* W_ukv = (const float*)d_in[6];
    const float* W_o   = (const float*)d_in[7];
    float* out = (float*)d_out;

    float *cc;
    h16 *Xh,*Wc,*Wuq,*Wukv,*Wo;
    h16 *cqh,*qh,*ckvnh,*krh,*kvh,*kTh,*sch,*Ph,*oh;

    cudaGetSymbolAddress((void**)&cc,  g_c);
    cudaGetSymbolAddress((void**)&Xh,  g_Xh);
    cudaGetSymbolAddress((void**)&Wc,  g_Wc);
    cudaGetSymbolAddress((void**)&Wuq,  g_Wuq);
    cudaGetSymbolAddress((void**)&Wukv, g_Wukv);
    cudaGetSymbolAddress((void**)&Wo,   g_Wo);
    cudaGetSymbolAddress((void**)&cqh, g_cqh);
    cudaGetSymbolAddress((void**)&qh,  g_qh);
    cudaGetSymbolAddress((void**)&ckvnh, g_ckvnh);
    cudaGetSymbolAddress((void**)&krh, g_krh);
    cudaGetSymbolAddress((void**)&kvh, g_kvh);
    cudaGetSymbolAddress((void**)&kTh, g_kTh);
    cudaGetSymbolAddress((void**)&sch, g_sch);
    cudaGetSymbolAddress((void**)&Ph,  g_Ph);
    cudaGetSymbolAddress((void**)&oh,  g_oh);

    cudaFuncSetAttribute(bgemm1, cudaFuncAttributeMaxDynamicSharedMemorySize, SMEM_BYTES);

    dim3 blk(256);
    const int SB = SMEM_BYTES;

    // ---- quantize inputs to fp16 (W_dq/W_dkv concatenated into Wc) ----
    long long nX = (long long)S_LEN * HIDDEN;
    quant16_kernel<<<split_grid(nX), blk>>>(X, Xh, nX);
    quant16_pad_kernel<<<split_grid((long long)HIDDEN * DQ), blk>>>(
        W_dq, Wc, (long long)HIDDEN * DQ, DQ, NC, 0);
    quant16_pad_kernel<<<split_grid((long long)HIDDEN * DCKV), blk>>>(
        W_dkv, Wc, (long long)HIDDEN * DCKV, DCKV, NC, DQ);
    quant16_kernel<<<split_grid((long long)DQ * NQCR), blk>>>(W_uq, Wuq, (long long)DQ * NQCR);
    quant16_kernel<<<split_grid((long long)DKV * NKV), blk>>>(W_ukv, Wukv, (long long)DKV * NKV);
    quant16_kernel<<<split_grid((long long)NODIM * HIDDEN), blk>>>(W_o, Wo, (long long)NODIM * HIDDEN);

    // ---- G1+G3 merged: c = X @ [W_dq | W_dkv]   [2048 x 2112] ----
    bgemm1<<<dim3((NC + 127) / 128, S_LEN / 128, 1), blk, SB>>>(
        S_LEN, NC, HIDDEN, Xh, HIDDEN, 0, Wc, NC, 0,
        cc, (h16*)0, NC, 0, 1.f);

    // rmsnorm c_q (cols 0..1535) -> fp16
    rmsnorm_quant_kernel<<<S_LEN, 256>>>(cc, gq, DQ, NC, DQ, cqh);
    // rmsnorm c_kv (cols 1536..2047) -> fp16
    rmsnorm_quant_kernel<<<S_LEN, 256>>>(cc + DQ, gkv, DKV, NC, DKV, ckvnh);
    // rope k_r (cols 2048..2111) -> fp16
    rope_k_kernel<<<S_LEN / 8, 256>>>(cc + DQ + DKV, NC, krh);

    // ---- G2: q = c_qn @ W_uq (fp16 out), then in-place rope on q_r ----
    bgemm1<<<dim3(NQCR / 128, S_LEN / 128, 1), blk, SB>>>(
        S_LEN, NQCR, DQ, cqh, DQ, 0, Wuq, NQCR, 0,
        (float*)0, qh, NQCR, 0, 1.f);

    rope_q16_kernel<<<(S_LEN * NH) / 8, 256>>>(qh);

    // ---- G4: kv = c_kvn @ W_ukv (fp16 out) ----
    bgemm1<<<dim3(NKV / 128, S_LEN / 128, 1), blk, SB>>>(
        S_LEN, NKV, DKV, ckvnh, DKV, 0, Wukv, NKV, 0,
        (float*)0, kvh, NKV, 0, 1.f);

    build_kT_kernel<<<4096, 256>>>(kvh, krh, kTh);

    // ---- G5: scores[h] = Q[h] @ K[h]^T * scale (fp16 out) ----
    float scale = 1.0f / sqrtf((float)DQR);
    bgemm1<<<dim3(S_LEN / 128, S_LEN / 128, NH), blk, SB>>>(
        S_LEN, S_LEN, DQR,
        qh, NQCR, (long long)DQR,
        kTh, S_LEN, (long long)DQR * S_LEN,
        (float*)0, sch, S_LEN, (long long)S_LEN * S_LEN, scale);

    softmax_fused_kernel<<<NH * S_LEN, 256>>>(sch, Ph);

    // ---- G6: O[h] = P[h] @ V[h] (fp16 out) ----
    bgemm1<<<dim3(1, S_LEN / 128, NH), blk, SB>>>(
        S_LEN, DH, S_LEN,
        Ph, S_LEN, (long long)S_LEN * S_LEN,
        kvh + DH, NKV, (long long)2 * DH,
        (float*)0, oh, NODIM, (long long)DH, 1.f);

    // ---- G7: out = O @ W_o ----
    bgemm1<<<dim3(HIDDEN / 128, S_LEN / 128, 1), blk, SB>>>(
        S_LEN, HIDDEN, NODIM, oh, NODIM, 0, Wo, HIDDEN, 0,
        out, (h16*)0, HIDDEN, 0, 1.f);
}